// round 1
// baseline (speedup 1.0000x reference)
#include <cuda_runtime.h>
#include <math.h>

#define NN 100000
#define EE 1600000
#define GG 512

// ---------------- scratch (device globals; no allocation allowed) ----------
__device__ float g_h[NN * 128];      // current activations
__device__ float g_t[NN * 128];      // h @ W (pre-aggregation)
__device__ float g_o[NN * 128];      // aggregated conv output
__device__ float g_deg[NN];
__device__ float g_dinv[NN];
__device__ unsigned g_pool[GG * 64];

// ---------------- degree / norm -------------------------------------------
__global__ void k_zero_deg() {
    int i = blockIdx.x * blockDim.x + threadIdx.x;
    if (i < NN) g_deg[i] = 0.0f;
}
__global__ void k_deg(const int* __restrict__ dst) {
    int e = blockIdx.x * blockDim.x + threadIdx.x;
    if (e < EE) atomicAdd(&g_deg[dst[e]], 1.0f);
}
__global__ void k_dinv() {
    int i = blockIdx.x * blockDim.x + threadIdx.x;
    if (i < NN) g_dinv[i] = rsqrtf(g_deg[i] + 1.0f);  // +1 self loop
}

// ---------------- GEMM: g_t = h @ W  (W is [DI,DO] row-major) -------------
// Block = 128 threads = 4 warps; each warp handles 8 nodes; lane holds DO/32 cols.
template <int DI, int DO>
__global__ void k_gemm(const float* __restrict__ h, const float* __restrict__ W) {
    constexpr int KK = (DI < 64) ? DI : 64;  // k-rows resident in smem per phase
    constexpr int P = DI / KK;               // phases (DI in {2,64,128})
    constexpr int C = DO / 32;               // cols per lane
    constexpr int WN = 8;                    // nodes per warp
    __shared__ float Ws[KK * DO];

    int lane = threadIdx.x & 31;
    int warp = threadIdx.x >> 5;
    int nbase = (blockIdx.x * 4 + warp) * WN;

    float acc[WN][C];
#pragma unroll
    for (int w = 0; w < WN; w++)
#pragma unroll
        for (int c = 0; c < C; c++) acc[w][c] = 0.0f;

    for (int p = 0; p < P; p++) {
        int k0 = p * KK;
        for (int i = threadIdx.x; i < KK * DO; i += 128) Ws[i] = W[k0 * DO + i];
        __syncthreads();

#pragma unroll
        for (int wn = 0; wn < WN; wn++) {
            int n = nbase + wn;
            if (n < NN) {  // uniform per warp
                float h0 = (lane < KK) ? h[n * DI + k0 + lane] : 0.0f;
                float h1 = (KK > 32 && lane + 32 < KK) ? h[n * DI + k0 + 32 + lane] : 0.0f;
#pragma unroll
                for (int k = 0; k < KK; k++) {
                    float hk = __shfl_sync(0xffffffffu, (k < 32) ? h0 : h1, k & 31);
#pragma unroll
                    for (int c = 0; c < C; c++) acc[wn][c] += hk * Ws[k * DO + lane + 32 * c];
                }
            }
        }
        __syncthreads();
    }

#pragma unroll
    for (int wn = 0; wn < WN; wn++) {
        int n = nbase + wn;
        if (n < NN) {
#pragma unroll
            for (int c = 0; c < C; c++) g_t[n * DO + lane + 32 * c] = acc[wn][c];
        }
    }
}

// ---------------- self-loop + bias init ------------------------------------
template <int DO>
__global__ void k_init(const float* __restrict__ b) {
    int i = blockIdx.x * blockDim.x + threadIdx.x;
    if (i < NN * DO) {
        int n = i / DO;
        int d = i % DO;
        float di = g_dinv[n];
        g_o[i] = b[d] + g_t[i] * di * di;
    }
}

// ---------------- edge scatter (gather src, atomic-add dst) ----------------
template <int DO>
__global__ void k_scatter(const int* __restrict__ src, const int* __restrict__ dst) {
    constexpr int C = DO / 4;  // float4 chunks per edge (power of 2)
    long long gid = (long long)blockIdx.x * blockDim.x + threadIdx.x;
    int e = (int)(gid / C);
    if (e < EE) {
        int c = (int)(gid & (C - 1));
        int s = src[e];
        int d = dst[e];
        float nrm = g_dinv[s] * g_dinv[d];
        const float4 v = *reinterpret_cast<const float4*>(&g_t[s * DO + 4 * c]);
        float* o = &g_o[d * DO + 4 * c];
        atomicAdd(o + 0, v.x * nrm);
        atomicAdd(o + 1, v.y * nrm);
        atomicAdd(o + 2, v.z * nrm);
        atomicAdd(o + 3, v.w * nrm);
    }
}

// ---------------- BN(eval) + exact GELU ------------------------------------
template <int DO, bool BN>
__global__ void k_act(const float* __restrict__ gam, const float* __restrict__ bet) {
    int i = blockIdx.x * blockDim.x + threadIdx.x;
    if (i < NN * DO) {
        float x = g_o[i];
        if (BN) {
            int d = i % DO;
            // inv = 1/sqrt(1 + 1e-5)
            x = x * (gam[d] * 0.99999500003749973f) + bet[d];
        }
        g_h[i] = 0.5f * x * (1.0f + erff(x * 0.70710678118654752f));
    }
}

// ---------------- segment max pool -----------------------------------------
__device__ __forceinline__ unsigned fenc(float x) {
    unsigned u = __float_as_uint(x);
    return (u & 0x80000000u) ? ~u : (u | 0x80000000u);
}
__device__ __forceinline__ float fdec(unsigned u) {
    return (u & 0x80000000u) ? __uint_as_float(u & 0x7fffffffu) : __uint_as_float(~u);
}

__global__ void k_pool_init() {
    int i = blockIdx.x * blockDim.x + threadIdx.x;
    if (i < GG * 64) g_pool[i] = 0u;
}
__global__ void k_pool(const int* __restrict__ batch) {
    int i = blockIdx.x * blockDim.x + threadIdx.x;
    if (i < NN * 64) {
        int n = i >> 6;
        int d = i & 63;
        atomicMax(&g_pool[batch[n] * 64 + d], fenc(g_h[i]));
    }
}

// ---------------- MLP head --------------------------------------------------
__global__ void k_head(const float* __restrict__ lw1, const float* __restrict__ lb1,
                       const float* __restrict__ lw2, const float* __restrict__ lb2,
                       float* __restrict__ out) {
    int g = blockIdx.x * blockDim.x + threadIdx.x;
    if (g < GG) {
        float p[64];
#pragma unroll
        for (int d = 0; d < 64; d++) p[d] = fdec(g_pool[g * 64 + d]);
        float o0 = lb2[0];
        float o1 = lb2[1];
#pragma unroll
        for (int j = 0; j < 10; j++) {
            float hj = lb1[j];
#pragma unroll
            for (int d = 0; d < 64; d++) hj += p[d] * lw1[d * 10 + j];
            o0 += hj * lw2[j * 2 + 0];
            o1 += hj * lw2[j * 2 + 1];
        }
        out[g * 2 + 0] = o0;
        out[g * 2 + 1] = o1;
    }
}

// ---------------- layer driver ----------------------------------------------
template <int DI, int DO, bool BN>
static void run_layer(const float* hin, const float* W, const float* b,
                      const float* gam, const float* bet,
                      const int* src, const int* dst) {
    k_gemm<DI, DO><<<(NN + 31) / 32, 128>>>(hin, W);
    k_init<DO><<<(NN * DO + 255) / 256, 256>>>(b);
    long long sth = (long long)EE * (DO / 4);
    k_scatter<DO><<<(unsigned)((sth + 255) / 256), 256>>>(src, dst);
    k_act<DO, BN><<<(NN * DO + 255) / 256, 256>>>(gam, bet);
}

extern "C" void kernel_launch(void* const* d_in, const int* in_sizes, int n_in,
                              void* d_out, int out_size) {
    const float* x = (const float*)d_in[0];
    const int* ei = (const int*)d_in[1];
    const int* src = ei;        // ei[0]
    const int* dst = ei + EE;   // ei[1]
    const int* batch = (const int*)d_in[2];
    const float* W1 = (const float*)d_in[3];
    const float* b1 = (const float*)d_in[4];
    const float* W2 = (const float*)d_in[5];
    const float* b2 = (const float*)d_in[6];
    const float* W3 = (const float*)d_in[7];
    const float* b3 = (const float*)d_in[8];
    const float* W4 = (const float*)d_in[9];
    const float* b4 = (const float*)d_in[10];
    const float* W5 = (const float*)d_in[11];
    const float* b5 = (const float*)d_in[12];
    const float* g1 = (const float*)d_in[13];
    const float* be1 = (const float*)d_in[14];
    const float* g2 = (const float*)d_in[15];
    const float* be2 = (const float*)d_in[16];
    const float* g3 = (const float*)d_in[17];
    const float* be3 = (const float*)d_in[18];
    const float* lw1 = (const float*)d_in[19];
    const float* lb1 = (const float*)d_in[20];
    const float* lw2 = (const float*)d_in[21];
    const float* lb2 = (const float*)d_in[22];
    float* out = (float*)d_out;

    float* hptr = nullptr;
    cudaGetSymbolAddress((void**)&hptr, g_h);

    // degree + norm
    k_zero_deg<<<(NN + 255) / 256, 256>>>();
    k_deg<<<(EE + 255) / 256, 256>>>(dst);
    k_dinv<<<(NN + 255) / 256, 256>>>();

    k_pool_init<<<(GG * 64 + 255) / 256, 256>>>();

    // 5 GCN layers
    run_layer<2, 64, true>(x, W1, b1, g1, be1, src, dst);
    run_layer<64, 64, false>(hptr, W2, b2, nullptr, nullptr, src, dst);
    run_layer<64, 128, true>(hptr, W3, b3, g2, be2, src, dst);
    run_layer<128, 128, false>(hptr, W4, b4, nullptr, nullptr, src, dst);
    run_layer<128, 64, true>(hptr, W5, b5, g3, be3, src, dst);

    // pool + head
    k_pool<<<(NN * 64 + 255) / 256, 256>>>(batch);
    k_head<<<2, 256>>>(lw1, lb1, lw2, lb2, out);
}

// round 4
// speedup vs baseline: 2.2716x; 2.2716x over previous
#include <cuda_runtime.h>
#include <math.h>

#define NN 100000
#define EE 1600000
#define GG 512

// ---------------- scratch (device globals; no allocation allowed) ----------
__device__ float g_h[NN * 128];      // activations (aggr output)
__device__ float g_t[NN * 128];      // h @ W (pre-aggregation)
__device__ float g_dinv[NN];
__device__ int   g_degi[NN];
__device__ int   g_off[NN + 1];
__device__ int   g_cursor[NN];
__device__ int   g_csrc[EE];
__device__ float g_cnrm[EE];
__device__ unsigned g_pool[GG * 64];

// ---------------- degree / norm / CSR --------------------------------------
__global__ void __launch_bounds__(256) k_zero() {
    int i = blockIdx.x * blockDim.x + threadIdx.x;
    if (i < NN) { g_degi[i] = 0; g_cursor[i] = 0; }
    if (i < GG * 64) g_pool[i] = 0u;
}
__global__ void __launch_bounds__(256) k_deg(const int* __restrict__ dst) {
    int e = blockIdx.x * blockDim.x + threadIdx.x;
    if (e < EE) atomicAdd(&g_degi[dst[e]], 1);
}
__global__ void __launch_bounds__(256) k_dinv() {
    int i = blockIdx.x * blockDim.x + threadIdx.x;
    if (i < NN) g_dinv[i] = rsqrtf((float)g_degi[i] + 1.0f);  // +1 self loop
}
// one-block exclusive scan of g_degi -> g_off
__global__ void __launch_bounds__(1024) k_scan() {
    __shared__ int s[1024];
    const int T = 1024;
    const int CH = (NN + T - 1) / T;
    int t = threadIdx.x;
    int base = t * CH;
    int sum = 0;
#pragma unroll 1
    for (int i = 0; i < CH; i++) { int idx = base + i; if (idx < NN) sum += g_degi[idx]; }
    s[t] = sum;
    __syncthreads();
    for (int o = 1; o < T; o <<= 1) {
        int v = (t >= o) ? s[t - o] : 0;
        __syncthreads();
        s[t] += v;
        __syncthreads();
    }
    int run = s[t] - sum;  // exclusive prefix
#pragma unroll 1
    for (int i = 0; i < CH; i++) {
        int idx = base + i;
        if (idx < NN) { g_off[idx] = run; run += g_degi[idx]; }
    }
    if (t == T - 1) g_off[NN] = EE;
}
__global__ void __launch_bounds__(256) k_fill(const int* __restrict__ src,
                                              const int* __restrict__ dst) {
    int e = blockIdx.x * blockDim.x + threadIdx.x;
    if (e < EE) {
        int s = src[e];
        int d = dst[e];
        int pos = g_off[d] + atomicAdd(&g_cursor[d], 1);
        g_csrc[pos] = s;
        g_cnrm[pos] = g_dinv[s] * g_dinv[d];
    }
}

// ---------------- GEMM: g_t = h @ W  (W is [DI,DO] row-major) --------------
template <int DI, int DO>
__global__ void __launch_bounds__(128) k_gemm(const float* __restrict__ h,
                                              const float* __restrict__ W) {
    constexpr int KK = (DI < 64) ? DI : 64;
    constexpr int P = DI / KK;
    constexpr int C = DO / 32;
    constexpr int WN = 8;
    __shared__ float Ws[KK * DO];

    int lane = threadIdx.x & 31;
    int warp = threadIdx.x >> 5;
    int nbase = (blockIdx.x * 4 + warp) * WN;

    float acc[WN][C];
#pragma unroll
    for (int w = 0; w < WN; w++)
#pragma unroll
        for (int c = 0; c < C; c++) acc[w][c] = 0.0f;

    for (int p = 0; p < P; p++) {
        int k0 = p * KK;
        for (int i = threadIdx.x; i < KK * DO; i += 128) Ws[i] = W[k0 * DO + i];
        __syncthreads();
#pragma unroll
        for (int wn = 0; wn < WN; wn++) {
            int n = nbase + wn;
            if (n < NN) {
                float h0 = (lane < KK) ? h[n * DI + k0 + lane] : 0.0f;
                float h1 = (KK > 32 && lane + 32 < KK) ? h[n * DI + k0 + 32 + lane] : 0.0f;
#pragma unroll
                for (int k = 0; k < KK; k++) {
                    float hk = __shfl_sync(0xffffffffu, (k < 32) ? h0 : h1, k & 31);
#pragma unroll
                    for (int c = 0; c < C; c++) acc[wn][c] += hk * Ws[k * DO + lane + 32 * c];
                }
            }
        }
        __syncthreads();
    }
#pragma unroll
    for (int wn = 0; wn < WN; wn++) {
        int n = nbase + wn;
        if (n < NN) {
#pragma unroll
            for (int c = 0; c < C; c++) g_t[n * DO + lane + 32 * c] = acc[wn][c];
        }
    }
}

// ---------------- pool encoding ---------------------------------------------
__device__ __forceinline__ unsigned fenc(float x) {
    unsigned u = __float_as_uint(x);
    return (u & 0x80000000u) ? ~u : (u | 0x80000000u);
}
__device__ __forceinline__ float fdec(unsigned u) {
    return (u & 0x80000000u) ? __uint_as_float(u & 0x7fffffffu) : __uint_as_float(~u);
}

// ---------------- fused CSR aggregation + selfloop + bias + BN + GELU -------
// warp per node; lanes own cols {lane, lane+32, ...}
template <int DO, bool BN, bool POOL>
__global__ void __launch_bounds__(256) k_aggr(const float* __restrict__ b,
                                              const float* __restrict__ gam,
                                              const float* __restrict__ bet,
                                              const int* __restrict__ batch) {
    constexpr int C = DO / 32;
    int lane = threadIdx.x & 31;
    int warp = threadIdx.x >> 5;
    int n = blockIdx.x * 8 + warp;
    if (n >= NN) return;

    float dn = g_dinv[n];
    float sl = dn * dn;
    float acc0[C], acc1[C];
#pragma unroll
    for (int c = 0; c < C; c++) {
        acc0[c] = sl * g_t[n * DO + lane + 32 * c];  // self loop
        acc1[c] = 0.0f;
    }

    int e = g_off[n];
    int r1 = g_off[n + 1];
    for (; e + 1 < r1; e += 2) {
        int s0 = g_csrc[e];
        int s1 = g_csrc[e + 1];
        float w0 = g_cnrm[e];
        float w1 = g_cnrm[e + 1];
#pragma unroll
        for (int c = 0; c < C; c++) {
            acc0[c] += w0 * __ldg(&g_t[s0 * DO + lane + 32 * c]);
            acc1[c] += w1 * __ldg(&g_t[s1 * DO + lane + 32 * c]);
        }
    }
    if (e < r1) {
        int s0 = g_csrc[e];
        float w0 = g_cnrm[e];
#pragma unroll
        for (int c = 0; c < C; c++) acc0[c] += w0 * __ldg(&g_t[s0 * DO + lane + 32 * c]);
    }

    int gb = POOL ? batch[n] : 0;
#pragma unroll
    for (int c = 0; c < C; c++) {
        int col = lane + 32 * c;
        float x = acc0[c] + acc1[c] + b[col];
        if (BN) x = x * (gam[col] * 0.99999500003749973f) + bet[col];
        float v = 0.5f * x * (1.0f + erff(x * 0.70710678118654752f));
        if (POOL)
            atomicMax(&g_pool[gb * 64 + col], fenc(v));
        else
            g_h[n * DO + col] = v;
    }
}

// ---------------- MLP head --------------------------------------------------
__global__ void __launch_bounds__(256) k_head(const float* __restrict__ lw1,
                                              const float* __restrict__ lb1,
                                              const float* __restrict__ lw2,
                                              const float* __restrict__ lb2,
                                              float* __restrict__ out) {
    int g = blockIdx.x * blockDim.x + threadIdx.x;
    if (g < GG) {
        float p[64];
#pragma unroll
        for (int d = 0; d < 64; d++) p[d] = fdec(g_pool[g * 64 + d]);
        float o0 = lb2[0];
        float o1 = lb2[1];
#pragma unroll
        for (int j = 0; j < 10; j++) {
            float hj = lb1[j];
#pragma unroll
            for (int d = 0; d < 64; d++) hj += p[d] * lw1[d * 10 + j];
            o0 += hj * lw2[j * 2 + 0];
            o1 += hj * lw2[j * 2 + 1];
        }
        out[g * 2 + 0] = o0;
        out[g * 2 + 1] = o1;
    }
}

// ---------------- layer driver ----------------------------------------------
template <int DI, int DO, bool BN, bool POOL>
static void run_layer(const float* hin, const float* W, const float* b,
                      const float* gam, const float* bet, const int* batch) {
    k_gemm<DI, DO><<<(NN + 31) / 32, 128>>>(hin, W);
    k_aggr<DO, BN, POOL><<<(NN + 7) / 8, 256>>>(b, gam, bet, batch);
}

extern "C" void kernel_launch(void* const* d_in, const int* in_sizes, int n_in,
                              void* d_out, int out_size) {
    const float* x = (const float*)d_in[0];
    const int* ei = (const int*)d_in[1];
    const int* src = ei;        // ei[0]
    const int* dst = ei + EE;   // ei[1]
    const int* batch = (const int*)d_in[2];
    const float* W1 = (const float*)d_in[3];
    const float* b1 = (const float*)d_in[4];
    const float* W2 = (const float*)d_in[5];
    const float* b2 = (const float*)d_in[6];
    const float* W3 = (const float*)d_in[7];
    const float* b3 = (const float*)d_in[8];
    const float* W4 = (const float*)d_in[9];
    const float* b4 = (const float*)d_in[10];
    const float* W5 = (const float*)d_in[11];
    const float* b5 = (const float*)d_in[12];
    const float* g1 = (const float*)d_in[13];
    const float* be1 = (const float*)d_in[14];
    const float* g2 = (const float*)d_in[15];
    const float* be2 = (const float*)d_in[16];
    const float* g3 = (const float*)d_in[17];
    const float* be3 = (const float*)d_in[18];
    const float* lw1 = (const float*)d_in[19];
    const float* lb1 = (const float*)d_in[20];
    const float* lw2 = (const float*)d_in[21];
    const float* lb2 = (const float*)d_in[22];
    float* out = (float*)d_out;

    float* hptr = nullptr;
    cudaGetSymbolAddress((void**)&hptr, g_h);

    // CSR build (per call; deterministic up to within-row order)
    // NOTE: k_zero must cover max(NN, GG*64) threads — it resets degi/cursor (NN)
    // AND the pool (GG*64).
    k_zero<<<(NN + 255) / 256, 256>>>();
    k_deg<<<(EE + 255) / 256, 256>>>(dst);
    k_dinv<<<(NN + 255) / 256, 256>>>();
    k_scan<<<1, 1024>>>();
    k_fill<<<(EE + 255) / 256, 256>>>(src, dst);

    // 5 GCN layers (last one fuses global_max_pool)
    run_layer<2, 64, true, false>(x, W1, b1, g1, be1, nullptr);
    run_layer<64, 64, false, false>(hptr, W2, b2, nullptr, nullptr, nullptr);
    run_layer<64, 128, true, false>(hptr, W3, b3, g2, be2, nullptr);
    run_layer<128, 128, false, false>(hptr, W4, b4, nullptr, nullptr, nullptr);
    run_layer<128, 64, true, true>(hptr, W5, b5, g3, be3, batch);

    k_head<<<2, 256>>>(lw1, lb1, lw2, lb2, out);
}

// round 5
// speedup vs baseline: 2.6931x; 1.1855x over previous
#include <cuda_runtime.h>
#include <math.h>

#define NN 100000
#define EE 1600000
#define GG 512

// ---------------- scratch (device globals; no allocation allowed) ----------
__device__ float g_h[NN * 128];      // dinv-scaled activations (layer input)
__device__ float g_a[NN * 128];      // aggregated (pre-GEMM) features
__device__ float g_t[NN * 128];      // L5 gemm output (pre-aggregation)
__device__ float g_dinv[NN];
__device__ int   g_degi[NN];
__device__ int   g_off[NN];
__device__ int   g_cursor[NN];
__device__ int   g_csrc[EE];
__device__ int   g_ctr;
__device__ unsigned g_pool[GG * 64];

// ---------------- degree / norm / CSR --------------------------------------
__global__ void __launch_bounds__(256) k_zero() {
    int i = blockIdx.x * blockDim.x + threadIdx.x;
    if (i < NN) { g_degi[i] = 0; g_cursor[i] = 0; }
    if (i < GG * 64) g_pool[i] = 0u;
    if (i == 0) g_ctr = 0;
}
__global__ void __launch_bounds__(256) k_deg(const int* __restrict__ dst) {
    int e = blockIdx.x * blockDim.x + threadIdx.x;
    if (e < EE) atomicAdd(&g_degi[dst[e]], 1);
}
// dinv + pre-scale the 2-wide input features
__global__ void __launch_bounds__(256) k_dinv(const float* __restrict__ x) {
    int i = blockIdx.x * blockDim.x + threadIdx.x;
    if (i < NN) {
        float di = rsqrtf((float)g_degi[i] + 1.0f);  // +1 self loop
        g_dinv[i] = di;
        g_h[i * 2 + 0] = di * x[i * 2 + 0];
        g_h[i * 2 + 1] = di * x[i * 2 + 1];
    }
}
// per-block scan + global atomic base (row placement order-free)
__global__ void __launch_bounds__(256) k_off() {
    int i = blockIdx.x * 256 + threadIdx.x;
    int lane = threadIdx.x & 31;
    int w = threadIdx.x >> 5;
    int v = (i < NN) ? g_degi[i] : 0;
    int x = v;
#pragma unroll
    for (int o = 1; o < 32; o <<= 1) {
        int y = __shfl_up_sync(0xffffffffu, x, o);
        if (lane >= o) x += y;
    }
    __shared__ int ws[8];
    __shared__ int base;
    if (lane == 31) ws[w] = x;
    __syncthreads();
    if (w == 0) {
        int s = (lane < 8) ? ws[lane] : 0;
#pragma unroll
        for (int o = 1; o < 8; o <<= 1) {
            int y = __shfl_up_sync(0xffffffffu, s, o);
            if (lane >= o) s += y;
        }
        if (lane < 8) ws[lane] = s;
    }
    __syncthreads();
    if (threadIdx.x == 0) base = atomicAdd(&g_ctr, ws[7]);
    int excl = x - v + ((w > 0) ? ws[w - 1] : 0);
    __syncthreads();
    if (i < NN) g_off[i] = base + excl;
}
__global__ void __launch_bounds__(256) k_fill(const int* __restrict__ src,
                                              const int* __restrict__ dst) {
    int e = blockIdx.x * blockDim.x + threadIdx.x;
    if (e < EE) {
        int d = dst[e];
        int pos = g_off[d] + atomicAdd(&g_cursor[d], 1);
        g_csrc[pos] = src[e];
    }
}

// ---------------- aggregation: out = dinv[d] * (in[d] + sum_nbr in[s]) -----
// DI=2 special case: thread per node
__global__ void __launch_bounds__(256) k_aggr_pre2() {
    int n = blockIdx.x * blockDim.x + threadIdx.x;
    if (n >= NN) return;
    const float2* hh = (const float2*)g_h;
    float2 acc = hh[n];
    int e = g_off[n];
    int r1 = e + g_degi[n];
    for (; e < r1; e++) {
        float2 v = __ldg(&hh[g_csrc[e]]);
        acc.x += v.x;
        acc.y += v.y;
    }
    float di = g_dinv[n];
    g_a[n * 2 + 0] = di * acc.x;
    g_a[n * 2 + 1] = di * acc.y;
}

// D in {64,128}: warp per node, lanes own stride-32 columns
template <int D>
__global__ void __launch_bounds__(256) k_aggr_pre() {
    constexpr int C = D / 32;
    int lane = threadIdx.x & 31;
    int warp = threadIdx.x >> 5;
    int n = blockIdx.x * 8 + warp;
    if (n >= NN) return;

    float acc0[C], acc1[C];
#pragma unroll
    for (int c = 0; c < C; c++) {
        acc0[c] = g_h[n * D + lane + 32 * c];  // self term
        acc1[c] = 0.0f;
    }
    int e = g_off[n];
    int r1 = e + g_degi[n];
    for (; e + 1 < r1; e += 2) {
        int s0 = g_csrc[e];
        int s1 = g_csrc[e + 1];
#pragma unroll
        for (int c = 0; c < C; c++) {
            acc0[c] += __ldg(&g_h[s0 * D + lane + 32 * c]);
            acc1[c] += __ldg(&g_h[s1 * D + lane + 32 * c]);
        }
    }
    if (e < r1) {
        int s0 = g_csrc[e];
#pragma unroll
        for (int c = 0; c < C; c++) acc0[c] += __ldg(&g_h[s0 * D + lane + 32 * c]);
    }
    float di = g_dinv[n];
#pragma unroll
    for (int c = 0; c < C; c++) g_a[n * D + lane + 32 * c] = di * (acc0[c] + acc1[c]);
}

// ---------------- GEMM (+ optional fused bias/BN/GELU/dinv epilogue) -------
// EPI=true: out = dinv * gelu(bn(acc+b)) -> g_h ;  EPI=false: acc -> g_t
template <int DI, int DO, bool EPI, bool BN>
__global__ void __launch_bounds__(128) k_gemm(const float* __restrict__ h,
                                              const float* __restrict__ W,
                                              const float* __restrict__ b,
                                              const float* __restrict__ gam,
                                              const float* __restrict__ bet) {
    constexpr int KK = (DI < 64) ? DI : 64;
    constexpr int P = DI / KK;
    constexpr int C = DO / 32;
    constexpr int WN = 8;
    __shared__ float Ws[KK * DO];

    int lane = threadIdx.x & 31;
    int warp = threadIdx.x >> 5;
    int nbase = (blockIdx.x * 4 + warp) * WN;

    float acc[WN][C];
#pragma unroll
    for (int w = 0; w < WN; w++)
#pragma unroll
        for (int c = 0; c < C; c++) acc[w][c] = 0.0f;

    for (int p = 0; p < P; p++) {
        int k0 = p * KK;
        for (int i = threadIdx.x; i < KK * DO; i += 128) Ws[i] = W[k0 * DO + i];
        __syncthreads();
#pragma unroll
        for (int wn = 0; wn < WN; wn++) {
            int n = nbase + wn;
            if (n < NN) {
                float h0 = (lane < KK) ? h[n * DI + k0 + lane] : 0.0f;
                float h1 = (KK > 32 && lane + 32 < KK) ? h[n * DI + k0 + 32 + lane] : 0.0f;
#pragma unroll
                for (int k = 0; k < KK; k++) {
                    float hk = __shfl_sync(0xffffffffu, (k < 32) ? h0 : h1, k & 31);
#pragma unroll
                    for (int c = 0; c < C; c++) acc[wn][c] += hk * Ws[k * DO + lane + 32 * c];
                }
            }
        }
        __syncthreads();
    }
#pragma unroll
    for (int wn = 0; wn < WN; wn++) {
        int n = nbase + wn;
        if (n < NN) {
            float di = EPI ? g_dinv[n] : 0.0f;
#pragma unroll
            for (int c = 0; c < C; c++) {
                int col = lane + 32 * c;
                if (EPI) {
                    float x = acc[wn][c] + b[col];
                    if (BN) x = x * (gam[col] * 0.99999500003749973f) + bet[col];
                    float v = 0.5f * x * (1.0f + erff(x * 0.70710678118654752f));
                    g_h[n * DO + col] = di * v;
                } else {
                    g_t[n * DO + col] = acc[wn][c];
                }
            }
        }
    }
}

// ---------------- pool encoding ---------------------------------------------
__device__ __forceinline__ unsigned fenc(float x) {
    unsigned u = __float_as_uint(x);
    return (u & 0x80000000u) ? ~u : (u | 0x80000000u);
}
__device__ __forceinline__ float fdec(unsigned u) {
    return (u & 0x80000000u) ? __uint_as_float(u & 0x7fffffffu) : __uint_as_float(~u);
}

// ---------------- L5: aggregate gemm output + bias + BN + GELU + pool -------
__global__ void __launch_bounds__(256) k_aggr_post(const float* __restrict__ b,
                                                   const float* __restrict__ gam,
                                                   const float* __restrict__ bet,
                                                   const int* __restrict__ batch) {
    constexpr int D = 64;
    constexpr int C = 2;
    int lane = threadIdx.x & 31;
    int warp = threadIdx.x >> 5;
    int n = blockIdx.x * 8 + warp;
    if (n >= NN) return;

    float acc0[C], acc1[C];
#pragma unroll
    for (int c = 0; c < C; c++) {
        acc0[c] = g_t[n * D + lane + 32 * c];
        acc1[c] = 0.0f;
    }
    int e = g_off[n];
    int r1 = e + g_degi[n];
    for (; e + 1 < r1; e += 2) {
        int s0 = g_csrc[e];
        int s1 = g_csrc[e + 1];
#pragma unroll
        for (int c = 0; c < C; c++) {
            acc0[c] += __ldg(&g_t[s0 * D + lane + 32 * c]);
            acc1[c] += __ldg(&g_t[s1 * D + lane + 32 * c]);
        }
    }
    if (e < r1) {
        int s0 = g_csrc[e];
#pragma unroll
        for (int c = 0; c < C; c++) acc0[c] += __ldg(&g_t[s0 * D + lane + 32 * c]);
    }
    float di = g_dinv[n];
    int gb = batch[n];
#pragma unroll
    for (int c = 0; c < C; c++) {
        int col = lane + 32 * c;
        float x = di * (acc0[c] + acc1[c]) + b[col];
        x = x * (gam[col] * 0.99999500003749973f) + bet[col];
        float v = 0.5f * x * (1.0f + erff(x * 0.70710678118654752f));
        atomicMax(&g_pool[gb * 64 + col], fenc(v));
    }
}

// ---------------- MLP head --------------------------------------------------
__global__ void __launch_bounds__(256) k_head(const float* __restrict__ lw1,
                                              const float* __restrict__ lb1,
                                              const float* __restrict__ lw2,
                                              const float* __restrict__ lb2,
                                              float* __restrict__ out) {
    int g = blockIdx.x * blockDim.x + threadIdx.x;
    if (g < GG) {
        float p[64];
#pragma unroll
        for (int d = 0; d < 64; d++) p[d] = fdec(g_pool[g * 64 + d]);
        float o0 = lb2[0];
        float o1 = lb2[1];
#pragma unroll
        for (int j = 0; j < 10; j++) {
            float hj = lb1[j];
#pragma unroll
            for (int d = 0; d < 64; d++) hj += p[d] * lw1[d * 10 + j];
            o0 += hj * lw2[j * 2 + 0];
            o1 += hj * lw2[j * 2 + 1];
        }
        out[g * 2 + 0] = o0;
        out[g * 2 + 1] = o1;
    }
}

extern "C" void kernel_launch(void* const* d_in, const int* in_sizes, int n_in,
                              void* d_out, int out_size) {
    const float* x = (const float*)d_in[0];
    const int* ei = (const int*)d_in[1];
    const int* src = ei;        // ei[0]
    const int* dst = ei + EE;   // ei[1]
    const int* batch = (const int*)d_in[2];
    const float* W1 = (const float*)d_in[3];
    const float* b1 = (const float*)d_in[4];
    const float* W2 = (const float*)d_in[5];
    const float* b2 = (const float*)d_in[6];
    const float* W3 = (const float*)d_in[7];
    const float* b3 = (const float*)d_in[8];
    const float* W4 = (const float*)d_in[9];
    const float* b4 = (const float*)d_in[10];
    const float* W5 = (const float*)d_in[11];
    const float* b5 = (const float*)d_in[12];
    const float* g1 = (const float*)d_in[13];
    const float* be1 = (const float*)d_in[14];
    const float* g2 = (const float*)d_in[15];
    const float* be2 = (const float*)d_in[16];
    const float* g3 = (const float*)d_in[17];
    const float* be3 = (const float*)d_in[18];
    const float* lw1 = (const float*)d_in[19];
    const float* lb1 = (const float*)d_in[20];
    const float* lw2 = (const float*)d_in[21];
    const float* lb2 = (const float*)d_in[22];
    float* out = (float*)d_out;

    float* aptr = nullptr;
    float* hptr = nullptr;
    cudaGetSymbolAddress((void**)&aptr, g_a);
    cudaGetSymbolAddress((void**)&hptr, g_h);

    // CSR build (no per-edge norms needed; rows placed by block-atomic scan)
    k_zero<<<(NN + 255) / 256, 256>>>();
    k_deg<<<(EE + 255) / 256, 256>>>(dst);
    k_dinv<<<(NN + 255) / 256, 256>>>(x);   // also writes scaled x into g_h
    k_off<<<(NN + 255) / 256, 256>>>();
    k_fill<<<(EE + 255) / 256, 256>>>(src, dst);

    // L1: aggregate (DI=2) then GEMM 2->64 + BN + GELU + dinv
    k_aggr_pre2<<<(NN + 255) / 256, 256>>>();
    k_gemm<2, 64, true, true><<<(NN + 31) / 32, 128>>>(aptr, W1, b1, g1, be1);
    // L2: aggregate (64) then GEMM 64->64 + GELU + dinv
    k_aggr_pre<64><<<(NN + 7) / 8, 256>>>();
    k_gemm<64, 64, true, false><<<(NN + 31) / 32, 128>>>(aptr, W2, b2, nullptr, nullptr);
    // L3: aggregate (64) then GEMM 64->128 + BN + GELU + dinv
    k_aggr_pre<64><<<(NN + 7) / 8, 256>>>();
    k_gemm<64, 128, true, true><<<(NN + 31) / 32, 128>>>(aptr, W3, b3, g2, be2);
    // L4: aggregate (128) then GEMM 128->128 + GELU + dinv
    k_aggr_pre<128><<<(NN + 7) / 8, 256>>>();
    k_gemm<128, 128, true, false><<<(NN + 31) / 32, 128>>>(aptr, W4, b4, nullptr, nullptr);
    // L5: GEMM 128->64 (plain, scaled input) then aggregate(64)+bias+BN+GELU+pool
    k_gemm<128, 64, false, false><<<(NN + 31) / 32, 128>>>(hptr, W5, nullptr, nullptr, nullptr);
    k_aggr_post<<<(NN + 7) / 8, 256>>>(b5, g3, be3, batch);

    k_head<<<2, 256>>>(lw1, lb1, lw2, lb2, out);
}

// round 7
// speedup vs baseline: 4.5098x; 1.6746x over previous
#include <cuda_runtime.h>
#include <math.h>

#define NN 100000
#define EE 1600000
#define GG 512

// ---------------- scratch (device globals; no allocation allowed) ----------
__device__ float g_h[NN * 128];      // dinv-scaled activations (layer input)
__device__ float g_a[NN * 128];      // aggregated (pre-GEMM) features
__device__ float g_t[NN * 128];      // L5 gemm output (pre-aggregation)
__device__ float g_dinv[NN];
__device__ int   g_degi[NN];
__device__ int   g_off[NN];
__device__ int   g_cursor[NN];
__device__ int   g_csrc[EE];
__device__ int   g_ctr;
__device__ unsigned g_pool[GG * 64];

// ---------------- CSR build --------------------------------------------------
__global__ void __launch_bounds__(256) k_zero() {
    int i = blockIdx.x * blockDim.x + threadIdx.x;
    if (i < NN) { g_degi[i] = 0; g_cursor[i] = 0; }
    if (i < GG * 64) g_pool[i] = 0u;
    if (i == 0) g_ctr = 0;
}
__global__ void __launch_bounds__(256) k_deg(const int* __restrict__ dst) {
    int e = blockIdx.x * blockDim.x + threadIdx.x;
    if (e < EE) atomicAdd(&g_degi[dst[e]], 1);
}
// fused: dinv + scaled input features + block-scan offsets (order-free base)
__global__ void __launch_bounds__(256) k_prep(const float* __restrict__ x) {
    int i = blockIdx.x * 256 + threadIdx.x;
    int lane = threadIdx.x & 31;
    int w = threadIdx.x >> 5;
    int v = (i < NN) ? g_degi[i] : 0;
    if (i < NN) {
        float di = rsqrtf((float)v + 1.0f);  // +1 self loop
        g_dinv[i] = di;
        g_h[i * 2 + 0] = di * x[i * 2 + 0];
        g_h[i * 2 + 1] = di * x[i * 2 + 1];
    }
    int xs = v;
#pragma unroll
    for (int o = 1; o < 32; o <<= 1) {
        int y = __shfl_up_sync(0xffffffffu, xs, o);
        if (lane >= o) xs += y;
    }
    __shared__ int ws[8];
    __shared__ int base;
    if (lane == 31) ws[w] = xs;
    __syncthreads();
    if (w == 0) {
        int s = (lane < 8) ? ws[lane] : 0;
#pragma unroll
        for (int o = 1; o < 8; o <<= 1) {
            int y = __shfl_up_sync(0xffffffffu, s, o);
            if (lane >= o) s += y;
        }
        if (lane < 8) ws[lane] = s;
    }
    __syncthreads();
    if (threadIdx.x == 0) base = atomicAdd(&g_ctr, ws[7]);
    int excl = xs - v + ((w > 0) ? ws[w - 1] : 0);
    __syncthreads();
    if (i < NN) g_off[i] = base + excl;
}
__global__ void __launch_bounds__(256) k_fill(const int* __restrict__ src,
                                              const int* __restrict__ dst) {
    int e = blockIdx.x * blockDim.x + threadIdx.x;
    if (e < EE) {
        int d = dst[e];
        int pos = g_off[d] + atomicAdd(&g_cursor[d], 1);
        g_csrc[pos] = src[e];
    }
}

// ---------------- aggregation: out = dinv[d]*(in[d] + sum_nbr in[s]) --------
// DI=2: thread per node
__global__ void __launch_bounds__(256) k_aggr_pre2() {
    int n = blockIdx.x * blockDim.x + threadIdx.x;
    if (n >= NN) return;
    const float2* hh = (const float2*)g_h;
    float2 acc = hh[n];
    int e = g_off[n];
    int r1 = e + g_degi[n];
    for (; e < r1; e++) {
        float2 v = __ldg(&hh[g_csrc[e]]);
        acc.x += v.x;
        acc.y += v.y;
    }
    float di = g_dinv[n];
    g_a[n * 2 + 0] = di * acc.x;
    g_a[n * 2 + 1] = di * acc.y;
}

// D=64: warp per node, lane owns cols {2l, 2l+1} -> float2 row vector
__global__ void __launch_bounds__(256) k_aggr64(const float* __restrict__ in,
                                                float* __restrict__ outp) {
    int lane = threadIdx.x & 31;
    int warp = threadIdx.x >> 5;
    int n = blockIdx.x * 8 + warp;
    if (n >= NN) return;
    const float2* H = (const float2*)in;
    float2 a0 = H[n * 32 + lane];
    float2 a1 = make_float2(0.f, 0.f);
    int e = g_off[n];
    int r1 = e + g_degi[n];
    for (; e + 1 < r1; e += 2) {
        float2 v0 = __ldg(&H[g_csrc[e] * 32 + lane]);
        float2 v1 = __ldg(&H[g_csrc[e + 1] * 32 + lane]);
        a0.x += v0.x; a0.y += v0.y;
        a1.x += v1.x; a1.y += v1.y;
    }
    if (e < r1) {
        float2 v0 = __ldg(&H[g_csrc[e] * 32 + lane]);
        a0.x += v0.x; a0.y += v0.y;
    }
    float di = g_dinv[n];
    ((float2*)outp)[n * 32 + lane] = make_float2(di * (a0.x + a1.x), di * (a0.y + a1.y));
}

// D=128: warp per node, lane owns cols {4l..4l+3} -> float4
__global__ void __launch_bounds__(256) k_aggr128() {
    int lane = threadIdx.x & 31;
    int warp = threadIdx.x >> 5;
    int n = blockIdx.x * 8 + warp;
    if (n >= NN) return;
    const float4* H = (const float4*)g_h;
    float4 a0 = H[n * 32 + lane];
    float4 a1 = make_float4(0.f, 0.f, 0.f, 0.f);
    int e = g_off[n];
    int r1 = e + g_degi[n];
    for (; e + 1 < r1; e += 2) {
        float4 v0 = __ldg(&H[g_csrc[e] * 32 + lane]);
        float4 v1 = __ldg(&H[g_csrc[e + 1] * 32 + lane]);
        a0.x += v0.x; a0.y += v0.y; a0.z += v0.z; a0.w += v0.w;
        a1.x += v1.x; a1.y += v1.y; a1.z += v1.z; a1.w += v1.w;
    }
    if (e < r1) {
        float4 v0 = __ldg(&H[g_csrc[e] * 32 + lane]);
        a0.x += v0.x; a0.y += v0.y; a0.z += v0.z; a0.w += v0.w;
    }
    float di = g_dinv[n];
    ((float4*)g_a)[n * 32 + lane] = make_float4(di * (a0.x + a1.x), di * (a0.y + a1.y),
                                                di * (a0.z + a1.z), di * (a0.w + a1.w));
}

// ---------------- GEMM: out = epilogue(h @ W) ------------------------------
// lane owns VL=DO/32 consecutive cols. k-outer loop: 1 vector LDS per k.
// EPI=true: g_h = dinv * gelu(bn(acc+b)) ; EPI=false: g_t = acc
template <int DI, int DO, bool EPI, bool BN>
__global__ void __launch_bounds__(128) k_gemm(const float* __restrict__ h,
                                              const float* __restrict__ W,
                                              const float* __restrict__ b,
                                              const float* __restrict__ gam,
                                              const float* __restrict__ bet) {
    constexpr int KK = (DI < 64) ? DI : 64;
    constexpr int P = DI / KK;
    constexpr int VL = DO / 32;   // 2 or 4
    constexpr int WN = 8;
    __shared__ float Ws[KK * DO];

    int lane = threadIdx.x & 31;
    int warp = threadIdx.x >> 5;
    int nbase = (blockIdx.x * 4 + warp) * WN;

    float acc[WN][VL];
#pragma unroll
    for (int w = 0; w < WN; w++)
#pragma unroll
        for (int c = 0; c < VL; c++) acc[w][c] = 0.0f;

    for (int p = 0; p < P; p++) {
        int k0 = p * KK;
        // vectorized weight stage
        for (int i = threadIdx.x; i < KK * DO / 4; i += 128)
            ((float4*)Ws)[i] = ((const float4*)(W + k0 * DO))[i];
        __syncthreads();

        // preload h rows (clamped for tail block; garbage acc never stored)
        float h0[WN], h1[WN];
#pragma unroll
        for (int wn = 0; wn < WN; wn++) {
            int n = nbase + wn;
            if (n >= NN) n = NN - 1;
            h0[wn] = (lane < KK) ? h[n * DI + k0 + lane] : 0.0f;
            h1[wn] = (KK > 32) ? ((lane + 32 < KK) ? h[n * DI + k0 + 32 + lane] : 0.0f) : 0.0f;
        }

#pragma unroll
        for (int k = 0; k < KK; k++) {
            float wv[VL];
#pragma unroll
            for (int c = 0; c < VL; c++) wv[c] = Ws[k * DO + VL * lane + c];
#pragma unroll
            for (int wn = 0; wn < WN; wn++) {
                float hk = __shfl_sync(0xffffffffu, (k < 32) ? h0[wn] : h1[wn], k & 31);
#pragma unroll
                for (int c = 0; c < VL; c++) acc[wn][c] += hk * wv[c];
            }
        }
        __syncthreads();
    }

#pragma unroll
    for (int wn = 0; wn < WN; wn++) {
        int n = nbase + wn;
        if (n < NN) {
            if (EPI) {
                float di = g_dinv[n];
#pragma unroll
                for (int c = 0; c < VL; c++) {
                    int col = VL * lane + c;
                    float x = acc[wn][c] + b[col];
                    if (BN) x = x * (gam[col] * 0.99999500003749973f) + bet[col];
                    float v = 0.5f * x * (1.0f + erff(x * 0.70710678118654752f));
                    acc[wn][c] = di * v;
                }
            }
            float* dstp = EPI ? g_h : g_t;
            if (VL == 4)
                ((float4*)dstp)[n * 32 + lane] =
                    make_float4(acc[wn][0], acc[wn][1], acc[wn][2], acc[wn][3 % VL]);
            else
                ((float2*)dstp)[n * 32 + lane] = make_float2(acc[wn][0], acc[wn][1 % VL]);
        }
    }
}

// ---------------- pool encoding ---------------------------------------------
__device__ __forceinline__ unsigned fenc(float x) {
    unsigned u = __float_as_uint(x);
    return (u & 0x80000000u) ? ~u : (u | 0x80000000u);
}
__device__ __forceinline__ float fdec(unsigned u) {
    return (u & 0x80000000u) ? __uint_as_float(u & 0x7fffffffu) : __uint_as_float(~u);
}

// ---------------- L5: aggregate gemm output + bias + BN + GELU + pool -------
__global__ void __launch_bounds__(256) k_aggr_post(const float* __restrict__ b,
                                                   const float* __restrict__ gam,
                                                   const float* __restrict__ bet,
                                                   const int* __restrict__ batch) {
    int lane = threadIdx.x & 31;
    int warp = threadIdx.x >> 5;
    int n = blockIdx.x * 8 + warp;
    if (n >= NN) return;
    const float2* T = (const float2*)g_t;
    float2 a0 = T[n * 32 + lane];
    float2 a1 = make_float2(0.f, 0.f);
    int e = g_off[n];
    int r1 = e + g_degi[n];
    for (; e + 1 < r1; e += 2) {
        float2 v0 = __ldg(&T[g_csrc[e] * 32 + lane]);
        float2 v1 = __ldg(&T[g_csrc[e + 1] * 32 + lane]);
        a0.x += v0.x; a0.y += v0.y;
        a1.x += v1.x; a1.y += v1.y;
    }
    if (e < r1) {
        float2 v0 = __ldg(&T[g_csrc[e] * 32 + lane]);
        a0.x += v0.x; a0.y += v0.y;
    }
    float di = g_dinv[n];
    int gb = batch[n];
    float s[2] = {di * (a0.x + a1.x), di * (a0.y + a1.y)};
#pragma unroll
    for (int c = 0; c < 2; c++) {
        int col = 2 * lane + c;
        float x = s[c] + b[col];
        x = x * (gam[col] * 0.99999500003749973f) + bet[col];
        float v = 0.5f * x * (1.0f + erff(x * 0.70710678118654752f));
        atomicMax(&g_pool[gb * 64 + col], fenc(v));
    }
}

// ---------------- MLP head --------------------------------------------------
__global__ void __launch_bounds__(256) k_head(const float* __restrict__ lw1,
                                              const float* __restrict__ lb1,
                                              const float* __restrict__ lw2,
                                              const float* __restrict__ lb2,
                                              float* __restrict__ out) {
    int g = blockIdx.x * blockDim.x + threadIdx.x;
    if (g < GG) {
        float p[64];
#pragma unroll
        for (int d = 0; d < 64; d++) p[d] = fdec(g_pool[g * 64 + d]);
        float o0 = lb2[0];
        float o1 = lb2[1];
#pragma unroll
        for (int j = 0; j < 10; j++) {
            float hj = lb1[j];
#pragma unroll
            for (int d = 0; d < 64; d++) hj += p[d] * lw1[d * 10 + j];
            o0 += hj * lw2[j * 2 + 0];
            o1 += hj * lw2[j * 2 + 1];
        }
        out[g * 2 + 0] = o0;
        out[g * 2 + 1] = o1;
    }
}

extern "C" void kernel_launch(void* const* d_in, const int* in_sizes, int n_in,
                              void* d_out, int out_size) {
    const float* x = (const float*)d_in[0];
    const int* ei = (const int*)d_in[1];
    const int* src = ei;        // ei[0]
    const int* dst = ei + EE;   // ei[1]
    const int* batch = (const int*)d_in[2];
    const float* W1 = (const float*)d_in[3];
    const float* b1 = (const float*)d_in[4];
    const float* W2 = (const float*)d_in[5];
    const float* b2 = (const float*)d_in[6];
    const float* W3 = (const float*)d_in[7];
    const float* b3 = (const float*)d_in[8];
    const float* W4 = (const float*)d_in[9];
    const float* b4 = (const float*)d_in[10];
    const float* W5 = (const float*)d_in[11];
    const float* b5 = (const float*)d_in[12];
    const float* g1 = (const float*)d_in[13];
    const float* be1 = (const float*)d_in[14];
    const float* g2 = (const float*)d_in[15];
    const float* be2 = (const float*)d_in[16];
    const float* g3 = (const float*)d_in[17];
    const float* be3 = (const float*)d_in[18];
    const float* lw1 = (const float*)d_in[19];
    const float* lb1 = (const float*)d_in[20];
    const float* lw2 = (const float*)d_in[21];
    const float* lb2 = (const float*)d_in[22];
    float* out = (float*)d_out;

    float* aptr = nullptr;
    float* hptr = nullptr;
    cudaGetSymbolAddress((void**)&aptr, g_a);
    cudaGetSymbolAddress((void**)&hptr, g_h);

    // CSR build
    k_zero<<<(NN + 255) / 256, 256>>>();
    k_deg<<<(EE + 255) / 256, 256>>>(dst);
    k_prep<<<(NN + 255) / 256, 256>>>(x);
    k_fill<<<(EE + 255) / 256, 256>>>(src, dst);

    // L1: aggregate (DI=2) then GEMM 2->64 + BN + GELU + dinv
    k_aggr_pre2<<<(NN + 255) / 256, 256>>>();
    k_gemm<2, 64, true, true><<<(NN + 31) / 32, 128>>>(aptr, W1, b1, g1, be1);
    // L2: aggregate(64) then GEMM 64->64 + GELU + dinv
    k_aggr64<<<(NN + 7) / 8, 256>>>(hptr, aptr);
    k_gemm<64, 64, true, false><<<(NN + 31) / 32, 128>>>(aptr, W2, b2, nullptr, nullptr);
    // L3: aggregate(64) then GEMM 64->128 + BN + GELU + dinv
    k_aggr64<<<(NN + 7) / 8, 256>>>(hptr, aptr);
    k_gemm<64, 128, true, true><<<(NN + 31) / 32, 128>>>(aptr, W3, b3, g2, be2);
    // L4: aggregate(128) then GEMM 128->128 + GELU + dinv
    k_aggr128<<<(NN + 7) / 8, 256>>>();
    k_gemm<128, 128, true, false><<<(NN + 31) / 32, 128>>>(aptr, W4, b4, nullptr, nullptr);
    // L5: GEMM 128->64 (plain) then aggregate(64)+bias+BN+GELU+pool
    k_gemm<128, 64, false, false><<<(NN + 31) / 32, 128>>>(hptr, W5, nullptr, nullptr, nullptr);
    k_aggr_post<<<(NN + 7) / 8, 256>>>(b5, g3, be3, batch);

    k_head<<<2, 256>>>(lw1, lb1, lw2, lb2, out);
}

// round 8
// speedup vs baseline: 5.3166x; 1.1789x over previous
#include <cuda_runtime.h>
#include <math.h>

#define NN 100000
#define EE 1600000
#define GG 512

// ---------------- scratch (device globals; no allocation allowed) ----------
__device__ float g_h[NN * 128];      // dinv-scaled activations (layer input)
__device__ float g_a[NN * 128];      // aggregated (pre-GEMM) features
__device__ float g_t[NN * 128];      // L5 gemm output (pre-aggregation)
__device__ float g_dinv[NN];
__device__ int   g_degi[NN];
__device__ int   g_off[NN];
__device__ int   g_cursor[NN];
__device__ int   g_csrc[EE];
__device__ int   g_ctr;
__device__ unsigned g_pool[GG * 64];

// ---------------- CSR build --------------------------------------------------
__global__ void __launch_bounds__(256) k_zero() {
    int i = blockIdx.x * blockDim.x + threadIdx.x;
    if (i < NN) g_degi[i] = 0;
    if (i < GG * 64) g_pool[i] = 0u;
    if (i == 0) g_ctr = 0;
}
__global__ void __launch_bounds__(256) k_deg(const int* __restrict__ dst) {
    int e = blockIdx.x * blockDim.x + threadIdx.x;
    if (e < EE) atomicAdd(&g_degi[dst[e]], 1);
}
// fused: dinv + scaled input features + block-scan offsets (order-free base)
__global__ void __launch_bounds__(256) k_prep(const float* __restrict__ x) {
    int i = blockIdx.x * 256 + threadIdx.x;
    int lane = threadIdx.x & 31;
    int w = threadIdx.x >> 5;
    int v = (i < NN) ? g_degi[i] : 0;
    if (i < NN) {
        float di = rsqrtf((float)v + 1.0f);  // +1 self loop
        g_dinv[i] = di;
        g_h[i * 2 + 0] = di * x[i * 2 + 0];
        g_h[i * 2 + 1] = di * x[i * 2 + 1];
    }
    int xs = v;
#pragma unroll
    for (int o = 1; o < 32; o <<= 1) {
        int y = __shfl_up_sync(0xffffffffu, xs, o);
        if (lane >= o) xs += y;
    }
    __shared__ int ws[8];
    __shared__ int base;
    if (lane == 31) ws[w] = xs;
    __syncthreads();
    if (w == 0) {
        int s = (lane < 8) ? ws[lane] : 0;
#pragma unroll
        for (int o = 1; o < 8; o <<= 1) {
            int y = __shfl_up_sync(0xffffffffu, s, o);
            if (lane >= o) s += y;
        }
        if (lane < 8) ws[lane] = s;
    }
    __syncthreads();
    if (threadIdx.x == 0) base = atomicAdd(&g_ctr, ws[7]);
    int excl = xs - v + ((w > 0) ? ws[w - 1] : 0);
    __syncthreads();
    if (i < NN) {
        int off = base + excl;
        g_off[i] = off;
        g_cursor[i] = off;   // fill uses cursor directly
    }
}
__global__ void __launch_bounds__(256) k_fill(const int* __restrict__ src,
                                              const int* __restrict__ dst) {
    int e = blockIdx.x * blockDim.x + threadIdx.x;
    if (e < EE) {
        int pos = atomicAdd(&g_cursor[dst[e]], 1);
        g_csrc[pos] = src[e];
    }
}

// ---------------- aggregation: out = dinv[d]*(in[d] + sum_nbr in[s]) --------
// DI=2: thread per node
__global__ void __launch_bounds__(256) k_aggr_pre2() {
    int n = blockIdx.x * blockDim.x + threadIdx.x;
    if (n >= NN) return;
    const float2* hh = (const float2*)g_h;
    float2 acc = hh[n];
    int e = g_off[n];
    int r1 = e + g_degi[n];
    for (; e < r1; e++) {
        float2 v = __ldg(&hh[g_csrc[e]]);
        acc.x += v.x;
        acc.y += v.y;
    }
    float di = g_dinv[n];
    g_a[n * 2 + 0] = di * acc.x;
    g_a[n * 2 + 1] = di * acc.y;
}

// D=64: warp per node, lane owns cols {2l, 2l+1}
__global__ void __launch_bounds__(256) k_aggr64(const float* __restrict__ in,
                                                float* __restrict__ outp) {
    int lane = threadIdx.x & 31;
    int warp = threadIdx.x >> 5;
    int n = blockIdx.x * 8 + warp;
    if (n >= NN) return;
    const float2* H = (const float2*)in;
    float2 a0 = H[n * 32 + lane];
    float2 a1 = make_float2(0.f, 0.f);
    int e = g_off[n];
    int r1 = e + g_degi[n];
    for (; e + 1 < r1; e += 2) {
        float2 v0 = __ldg(&H[g_csrc[e] * 32 + lane]);
        float2 v1 = __ldg(&H[g_csrc[e + 1] * 32 + lane]);
        a0.x += v0.x; a0.y += v0.y;
        a1.x += v1.x; a1.y += v1.y;
    }
    if (e < r1) {
        float2 v0 = __ldg(&H[g_csrc[e] * 32 + lane]);
        a0.x += v0.x; a0.y += v0.y;
    }
    float di = g_dinv[n];
    ((float2*)outp)[n * 32 + lane] = make_float2(di * (a0.x + a1.x), di * (a0.y + a1.y));
}

// D=128: warp per node, lane owns cols {4l..4l+3}
__global__ void __launch_bounds__(256) k_aggr128() {
    int lane = threadIdx.x & 31;
    int warp = threadIdx.x >> 5;
    int n = blockIdx.x * 8 + warp;
    if (n >= NN) return;
    const float4* H = (const float4*)g_h;
    float4 a0 = H[n * 32 + lane];
    float4 a1 = make_float4(0.f, 0.f, 0.f, 0.f);
    int e = g_off[n];
    int r1 = e + g_degi[n];
    for (; e + 1 < r1; e += 2) {
        float4 v0 = __ldg(&H[g_csrc[e] * 32 + lane]);
        float4 v1 = __ldg(&H[g_csrc[e + 1] * 32 + lane]);
        a0.x += v0.x; a0.y += v0.y; a0.z += v0.z; a0.w += v0.w;
        a1.x += v1.x; a1.y += v1.y; a1.z += v1.z; a1.w += v1.w;
    }
    if (e < r1) {
        float4 v0 = __ldg(&H[g_csrc[e] * 32 + lane]);
        a0.x += v0.x; a0.y += v0.y; a0.z += v0.z; a0.w += v0.w;
    }
    float di = g_dinv[n];
    ((float4*)g_a)[n * 32 + lane] = make_float4(di * (a0.x + a1.x), di * (a0.y + a1.y),
                                                di * (a0.z + a1.z), di * (a0.w + a1.w));
}

// ---------------- epilogue helper -------------------------------------------
__device__ __forceinline__ float gelu_bn(float x, float bb, float gg, float be, bool bn) {
    x = x + bb;
    if (bn) x = x * (gg * 0.99999500003749973f) + be;
    return 0.5f * x * (1.0f + erff(x * 0.70710678118654752f));
}

// ---------------- L1: out = epi(a @ W1) for DI=2 ----------------------------
__global__ void __launch_bounds__(256) k_l1(const float* __restrict__ W,
                                            const float* __restrict__ b,
                                            const float* __restrict__ gam,
                                            const float* __restrict__ bet) {
    int lane = threadIdx.x & 31;
    int warp = threadIdx.x >> 5;
    int n = blockIdx.x * 8 + warp;
    if (n >= NN) return;
    float2 a = ((const float2*)g_a)[n];
    float2 w0 = __ldg(&((const float2*)W)[lane]);          // W[0][2l..2l+1]
    float2 w1 = __ldg(&((const float2*)(W + 64))[lane]);   // W[1][2l..2l+1]
    float2 bb = __ldg(&((const float2*)b)[lane]);
    float2 gg = __ldg(&((const float2*)gam)[lane]);
    float2 be = __ldg(&((const float2*)bet)[lane]);
    float di = g_dinv[n];
    float x0 = a.x * w0.x + a.y * w1.x;
    float x1 = a.x * w0.y + a.y * w1.y;
    x0 = di * gelu_bn(x0, bb.x, gg.x, be.x, true);
    x1 = di * gelu_bn(x1, bb.y, gg.y, be.y, true);
    ((float2*)g_h)[n * 32 + lane] = make_float2(x0, x1);
}

// ---------------- register-tiled outer-product GEMM -------------------------
// 256 threads; thread (tx,ty) computes 8 nodes x 4 cols.
// EPI=true: g_h = dinv * gelu(bn(acc+b)) ; EPI=false: g_t = acc
template <int DI, int DO, bool EPI, bool BN>
__global__ void __launch_bounds__(256) k_gemmT(const float* __restrict__ h,
                                               const float* __restrict__ W,
                                               const float* __restrict__ b,
                                               const float* __restrict__ gam,
                                               const float* __restrict__ bet) {
    constexpr int KK = 32;            // k slab
    constexpr int CT = DO / 4;        // col threads (32 or 16)
    constexpr int RT = 256 / CT;      // row threads (8 or 16)
    constexpr int MT = RT * 8;        // nodes per block (64 or 128)
    constexpr int K4 = KK / 4;
    __shared__ float hs[KK][MT + 4];  // transposed h slab (padded)
    __shared__ float ws[KK * DO];     // w slab

    int tid = threadIdx.x;
    int tx = tid % CT;
    int ty = tid / CT;
    int n0 = blockIdx.x * MT;

    float acc[8][4];
#pragma unroll
    for (int i = 0; i < 8; i++)
#pragma unroll
        for (int j = 0; j < 4; j++) acc[i][j] = 0.0f;

    for (int k0 = 0; k0 < DI; k0 += KK) {
        // stage h slab transposed: hs[k][n_local]
        for (int it = tid; it < MT * K4; it += 256) {
            int nl = it / K4;
            int k4 = it % K4;
            int n = n0 + nl;
            if (n >= NN) n = NN - 1;
            float4 v = __ldg((const float4*)&h[n * DI + k0 + 4 * k4]);
            hs[4 * k4 + 0][nl] = v.x;
            hs[4 * k4 + 1][nl] = v.y;
            hs[4 * k4 + 2][nl] = v.z;
            hs[4 * k4 + 3][nl] = v.w;
        }
        // stage w slab
        for (int it = tid; it < KK * DO / 4; it += 256)
            ((float4*)ws)[it] = __ldg(&((const float4*)(W + k0 * DO))[it]);
        __syncthreads();

#pragma unroll
        for (int k = 0; k < KK; k++) {
            float4 w4 = *(const float4*)&ws[k * DO + 4 * tx];
            float4 hA = *(const float4*)&hs[k][8 * ty];
            float4 hB = *(const float4*)&hs[k][8 * ty + 4];
            float hr[8] = {hA.x, hA.y, hA.z, hA.w, hB.x, hB.y, hB.z, hB.w};
            float wr[4] = {w4.x, w4.y, w4.z, w4.w};
#pragma unroll
            for (int i = 0; i < 8; i++)
#pragma unroll
                for (int j = 0; j < 4; j++) acc[i][j] += hr[i] * wr[j];
        }
        __syncthreads();
    }

    float4 bb = EPI ? __ldg((const float4*)&b[4 * tx]) : make_float4(0, 0, 0, 0);
    float4 gg = (EPI && BN) ? __ldg((const float4*)&gam[4 * tx]) : make_float4(0, 0, 0, 0);
    float4 be = (EPI && BN) ? __ldg((const float4*)&bet[4 * tx]) : make_float4(0, 0, 0, 0);
    float* dstp = EPI ? g_h : g_t;
#pragma unroll
    for (int i = 0; i < 8; i++) {
        int n = n0 + 8 * ty + i;
        if (n < NN) {
            float4 o;
            if (EPI) {
                float di = g_dinv[n];
                o.x = di * gelu_bn(acc[i][0], bb.x, gg.x, be.x, BN);
                o.y = di * gelu_bn(acc[i][1], bb.y, gg.y, be.y, BN);
                o.z = di * gelu_bn(acc[i][2], bb.z, gg.z, be.z, BN);
                o.w = di * gelu_bn(acc[i][3], bb.w, gg.w, be.w, BN);
            } else {
                o = make_float4(acc[i][0], acc[i][1], acc[i][2], acc[i][3]);
            }
            *(float4*)&dstp[n * DO + 4 * tx] = o;
        }
    }
}

// ---------------- pool encoding ---------------------------------------------
__device__ __forceinline__ unsigned fenc(float x) {
    unsigned u = __float_as_uint(x);
    return (u & 0x80000000u) ? ~u : (u | 0x80000000u);
}
__device__ __forceinline__ float fdec(unsigned u) {
    return (u & 0x80000000u) ? __uint_as_float(u & 0x7fffffffu) : __uint_as_float(~u);
}

// ---------------- L5: aggregate gemm output + bias + BN + GELU + pool -------
__global__ void __launch_bounds__(256) k_aggr_post(const float* __restrict__ b,
                                                   const float* __restrict__ gam,
                                                   const float* __restrict__ bet,
                                                   const int* __restrict__ batch) {
    int lane = threadIdx.x & 31;
    int warp = threadIdx.x >> 5;
    int n = blockIdx.x * 8 + warp;
    if (n >= NN) return;
    const float2* T = (const float2*)g_t;
    float2 a0 = T[n * 32 + lane];
    float2 a1 = make_float2(0.f, 0.f);
    int e = g_off[n];
    int r1 = e + g_degi[n];
    for (; e + 1 < r1; e += 2) {
        float2 v0 = __ldg(&T[g_csrc[e] * 32 + lane]);
        float2 v1 = __ldg(&T[g_csrc[e + 1] * 32 + lane]);
        a0.x += v0.x; a0.y += v0.y;
        a1.x += v1.x; a1.y += v1.y;
    }
    if (e < r1) {
        float2 v0 = __ldg(&T[g_csrc[e] * 32 + lane]);
        a0.x += v0.x; a0.y += v0.y;
    }
    float di = g_dinv[n];
    int gb = batch[n];
    float2 bb = __ldg(&((const float2*)b)[lane]);
    float2 gg = __ldg(&((const float2*)gam)[lane]);
    float2 be = __ldg(&((const float2*)bet)[lane]);
    float v0 = gelu_bn(di * (a0.x + a1.x), bb.x, gg.x, be.x, true);
    float v1 = gelu_bn(di * (a0.y + a1.y), bb.y, gg.y, be.y, true);
    atomicMax(&g_pool[gb * 64 + 2 * lane + 0], fenc(v0));
    atomicMax(&g_pool[gb * 64 + 2 * lane + 1], fenc(v1));
}

// ---------------- MLP head --------------------------------------------------
__global__ void __launch_bounds__(256) k_head(const float* __restrict__ lw1,
                                              const float* __restrict__ lb1,
                                              const float* __restrict__ lw2,
                                              const float* __restrict__ lb2,
                                              float* __restrict__ out) {
    int g = blockIdx.x * blockDim.x + threadIdx.x;
    if (g < GG) {
        float p[64];
#pragma unroll
        for (int d = 0; d < 64; d++) p[d] = fdec(g_pool[g * 64 + d]);
        float o0 = lb2[0];
        float o1 = lb2[1];
#pragma unroll
        for (int j = 0; j < 10; j++) {
            float hj = lb1[j];
#pragma unroll
            for (int d = 0; d < 64; d++) hj += p[d] * lw1[d * 10 + j];
            o0 += hj * lw2[j * 2 + 0];
            o1 += hj * lw2[j * 2 + 1];
        }
        out[g * 2 + 0] = o0;
        out[g * 2 + 1] = o1;
    }
}

extern "C" void kernel_launch(void* const* d_in, const int* in_sizes, int n_in,
                              void* d_out, int out_size) {
    const float* x = (const float*)d_in[0];
    const int* ei = (const int*)d_in[1];
    const int* src = ei;        // ei[0]
    const int* dst = ei + EE;   // ei[1]
    const int* batch = (const int*)d_in[2];
    const float* W1 = (const float*)d_in[3];
    const float* b1 = (const float*)d_in[4];
    const float* W2 = (const float*)d_in[5];
    const float* b2 = (const float*)d_in[6];
    const float* W3 = (const float*)d_in[7];
    const float* b3 = (const float*)d_in[8];
    const float* W4 = (const float*)d_in[9];
    const float* b4 = (const float*)d_in[10];
    const float* W5 = (const float*)d_in[11];
    const float* b5 = (const float*)d_in[12];
    const float* g1 = (const float*)d_in[13];
    const float* be1 = (const float*)d_in[14];
    const float* g2 = (const float*)d_in[15];
    const float* be2 = (const float*)d_in[16];
    const float* g3 = (const float*)d_in[17];
    const float* be3 = (const float*)d_in[18];
    const float* lw1 = (const float*)d_in[19];
    const float* lb1 = (const float*)d_in[20];
    const float* lw2 = (const float*)d_in[21];
    const float* lb2 = (const float*)d_in[22];
    float* out = (float*)d_out;

    float* aptr = nullptr;
    float* hptr = nullptr;
    cudaGetSymbolAddress((void**)&aptr, g_a);
    cudaGetSymbolAddress((void**)&hptr, g_h);

    // CSR build
    k_zero<<<(NN + 255) / 256, 256>>>();
    k_deg<<<(EE + 255) / 256, 256>>>(dst);
    k_prep<<<(NN + 255) / 256, 256>>>(x);
    k_fill<<<(EE + 255) / 256, 256>>>(src, dst);

    // L1: aggregate (DI=2) then tiny GEMM 2->64 + BN + GELU + dinv
    k_aggr_pre2<<<(NN + 255) / 256, 256>>>();
    k_l1<<<(NN + 7) / 8, 256>>>(W1, b1, g1, be1);
    // L2: aggregate(64) then GEMM 64->64 + GELU + dinv  (MT=128)
    k_aggr64<<<(NN + 7) / 8, 256>>>(hptr, aptr);
    k_gemmT<64, 64, true, false><<<(NN + 127) / 128, 256>>>(aptr, W2, b2, nullptr, nullptr);
    // L3: aggregate(64) then GEMM 64->128 + BN + GELU + dinv  (MT=64)
    k_aggr64<<<(NN + 7) / 8, 256>>>(hptr, aptr);
    k_gemmT<64, 128, true, true><<<(NN + 63) / 64, 256>>>(aptr, W3, b3, g2, be2);
    // L4: aggregate(128) then GEMM 128->128 + GELU + dinv  (MT=64)
    k_aggr128<<<(NN + 7) / 8, 256>>>();
    k_gemmT<128, 128, true, false><<<(NN + 63) / 64, 256>>>(aptr, W4, b4, nullptr, nullptr);
    // L5: GEMM 128->64 (plain, MT=128) then aggregate(64)+bias+BN+GELU+pool
    k_gemmT<128, 64, false, false><<<(NN + 127) / 128, 256>>>(hptr, W5, nullptr, nullptr, nullptr);
    k_aggr_post<<<(NN + 7) / 8, 256>>>(b5, g3, be3, batch);

    k_head<<<2, 256>>>(lw1, lb1, lw2, lb2, out);
}

// round 10
// speedup vs baseline: 5.4918x; 1.0330x over previous
#include <cuda_runtime.h>
#include <math.h>

#define NN 100000
#define EE 1600000
#define GG 512

// ---------------- scratch (device globals; no allocation allowed) ----------
__device__ float g_h[NN * 128];      // dinv-scaled activations (layer input)
__device__ float g_a[NN * 128];      // aggregated (pre-GEMM) features
__device__ float g_t[NN * 128];      // L5 gemm output (pre-aggregation)
__device__ float g_dinv[NN];
__device__ int   g_degi[NN];
__device__ int   g_off[NN];
__device__ int   g_cursor[NN];
__device__ int   g_csrc[EE];
__device__ int   g_ctr;
__device__ unsigned g_pool[GG * 64];

// ---------------- packed f32x2 helpers (Blackwell FFMA2) --------------------
__device__ __forceinline__ unsigned long long pack2(float v) {
    unsigned long long r;
    asm("mov.b64 %0, {%1, %1};" : "=l"(r) : "f"(v));
    return r;
}
__device__ __forceinline__ void unpack2(unsigned long long v, float& lo, float& hi) {
    asm("mov.b64 {%0, %1}, %2;" : "=f"(lo), "=f"(hi) : "l"(v));
}
__device__ __forceinline__ void fma2(unsigned long long& d, unsigned long long a,
                                     unsigned long long b) {
    asm("fma.rn.f32x2 %0, %1, %2, %0;" : "+l"(d) : "l"(a), "l"(b));
}

// ---------------- CSR build --------------------------------------------------
__global__ void __launch_bounds__(256) k_zero() {
    int i = blockIdx.x * blockDim.x + threadIdx.x;
    if (i < NN) g_degi[i] = 0;
    if (i < GG * 64) g_pool[i] = 0u;
    if (i == 0) g_ctr = 0;
}
__global__ void __launch_bounds__(256) k_deg(const int* __restrict__ dst) {
    int e = blockIdx.x * blockDim.x + threadIdx.x;
    if (e < EE) atomicAdd(&g_degi[dst[e]], 1);
}
// fused: dinv + scaled input features + block-scan offsets (order-free base)
__global__ void __launch_bounds__(256) k_prep(const float* __restrict__ x) {
    int i = blockIdx.x * 256 + threadIdx.x;
    int lane = threadIdx.x & 31;
    int w = threadIdx.x >> 5;
    int v = (i < NN) ? g_degi[i] : 0;
    if (i < NN) {
        float di = rsqrtf((float)v + 1.0f);  // +1 self loop
        g_dinv[i] = di;
        g_h[i * 2 + 0] = di * x[i * 2 + 0];
        g_h[i * 2 + 1] = di * x[i * 2 + 1];
    }
    int xs = v;
#pragma unroll
    for (int o = 1; o < 32; o <<= 1) {
        int y = __shfl_up_sync(0xffffffffu, xs, o);
        if (lane >= o) xs += y;
    }
    __shared__ int ws[8];
    __shared__ int base;
    if (lane == 31) ws[w] = xs;
    __syncthreads();
    if (w == 0) {
        int s = (lane < 8) ? ws[lane] : 0;
#pragma unroll
        for (int o = 1; o < 8; o <<= 1) {
            int y = __shfl_up_sync(0xffffffffu, s, o);
            if (lane >= o) s += y;
        }
        if (lane < 8) ws[lane] = s;
    }
    __syncthreads();
    if (threadIdx.x == 0) base = atomicAdd(&g_ctr, ws[7]);
    int excl = xs - v + ((w > 0) ? ws[w - 1] : 0);
    __syncthreads();
    if (i < NN) {
        int off = base + excl;
        g_off[i] = off;
        g_cursor[i] = off;   // fill uses cursor directly
    }
}
__global__ void __launch_bounds__(256) k_fill(const int* __restrict__ src,
                                              const int* __restrict__ dst) {
    int e = blockIdx.x * blockDim.x + threadIdx.x;
    if (e < EE) {
        int pos = atomicAdd(&g_cursor[dst[e]], 1);
        g_csrc[pos] = src[e];
    }
}

// ---------------- aggregation: out = dinv[d]*(in[d] + sum_nbr in[s]) --------
// DI=2: thread per node
__global__ void __launch_bounds__(256) k_aggr_pre2() {
    int n = blockIdx.x * blockDim.x + threadIdx.x;
    if (n >= NN) return;
    const float2* hh = (const float2*)g_h;
    float2 acc = hh[n];
    int e = g_off[n];
    int r1 = e + g_degi[n];
    for (; e < r1; e++) {
        float2 v = __ldg(&hh[g_csrc[e]]);
        acc.x += v.x;
        acc.y += v.y;
    }
    float di = g_dinv[n];
    g_a[n * 2 + 0] = di * acc.x;
    g_a[n * 2 + 1] = di * acc.y;
}

// D=64: warp per node, lane owns cols {2l, 2l+1}
__global__ void __launch_bounds__(256) k_aggr64(const float* __restrict__ in,
                                                float* __restrict__ outp) {
    int lane = threadIdx.x & 31;
    int warp = threadIdx.x >> 5;
    int n = blockIdx.x * 8 + warp;
    if (n >= NN) return;
    const float2* H = (const float2*)in;
    float2 a0 = H[n * 32 + lane];
    float2 a1 = make_float2(0.f, 0.f);
    int e = g_off[n];
    int r1 = e + g_degi[n];
    for (; e + 1 < r1; e += 2) {
        float2 v0 = __ldg(&H[g_csrc[e] * 32 + lane]);
        float2 v1 = __ldg(&H[g_csrc[e + 1] * 32 + lane]);
        a0.x += v0.x; a0.y += v0.y;
        a1.x += v1.x; a1.y += v1.y;
    }
    if (e < r1) {
        float2 v0 = __ldg(&H[g_csrc[e] * 32 + lane]);
        a0.x += v0.x; a0.y += v0.y;
    }
    float di = g_dinv[n];
    ((float2*)outp)[n * 32 + lane] = make_float2(di * (a0.x + a1.x), di * (a0.y + a1.y));
}

// D=128: warp per node, lane owns cols {4l..4l+3}
__global__ void __launch_bounds__(256) k_aggr128() {
    int lane = threadIdx.x & 31;
    int warp = threadIdx.x >> 5;
    int n = blockIdx.x * 8 + warp;
    if (n >= NN) return;
    const float4* H = (const float4*)g_h;
    float4 a0 = H[n * 32 + lane];
    float4 a1 = make_float4(0.f, 0.f, 0.f, 0.f);
    int e = g_off[n];
    int r1 = e + g_degi[n];
    for (; e + 1 < r1; e += 2) {
        float4 v0 = __ldg(&H[g_csrc[e] * 32 + lane]);
        float4 v1 = __ldg(&H[g_csrc[e + 1] * 32 + lane]);
        a0.x += v0.x; a0.y += v0.y; a0.z += v0.z; a0.w += v0.w;
        a1.x += v1.x; a1.y += v1.y; a1.z += v1.z; a1.w += v1.w;
    }
    if (e < r1) {
        float4 v0 = __ldg(&H[g_csrc[e] * 32 + lane]);
        a0.x += v0.x; a0.y += v0.y; a0.z += v0.z; a0.w += v0.w;
    }
    float di = g_dinv[n];
    ((float4*)g_a)[n * 32 + lane] = make_float4(di * (a0.x + a1.x), di * (a0.y + a1.y),
                                                di * (a0.z + a1.z), di * (a0.w + a1.w));
}

// ---------------- epilogue helper -------------------------------------------
__device__ __forceinline__ float gelu_bn(float x, float bb, float gg, float be, bool bn) {
    x = x + bb;
    if (bn) x = x * (gg * 0.99999500003749973f) + be;
    return 0.5f * x * (1.0f + erff(x * 0.70710678118654752f));
}

// ---------------- L1: out = epi(a @ W1) for DI=2 ----------------------------
__global__ void __launch_bounds__(256) k_l1(const float* __restrict__ W,
                                            const float* __restrict__ b,
                                            const float* __restrict__ gam,
                                            const float* __restrict__ bet) {
    int lane = threadIdx.x & 31;
    int warp = threadIdx.x >> 5;
    int n = blockIdx.x * 8 + warp;
    if (n >= NN) return;
    float2 a = ((const float2*)g_a)[n];
    float2 w0 = __ldg(&((const float2*)W)[lane]);          // W[0][2l..2l+1]
    float2 w1 = __ldg(&((const float2*)(W + 64))[lane]);   // W[1][2l..2l+1]
    float2 bb = __ldg(&((const float2*)b)[lane]);
    float2 gg = __ldg(&((const float2*)gam)[lane]);
    float2 be = __ldg(&((const float2*)bet)[lane]);
    float di = g_dinv[n];
    float x0 = a.x * w0.x + a.y * w1.x;
    float x1 = a.x * w0.y + a.y * w1.y;
    x0 = di * gelu_bn(x0, bb.x, gg.x, be.x, true);
    x1 = di * gelu_bn(x1, bb.y, gg.y, be.y, true);
    ((float2*)g_h)[n * 32 + lane] = make_float2(x0, x1);
}

// ---------------- register-tiled outer-product GEMM (FFMA2 inner loop) ------
// 256 threads; thread (tx,ty) computes 8 nodes x 4 cols (= 2 f32x2 pairs).
// EPI=true: g_h = dinv * gelu(bn(acc+b)) ; EPI=false: g_t = acc
template <int DI, int DO, bool EPI, bool BN>
__global__ void __launch_bounds__(256) k_gemmT(const float* __restrict__ h,
                                               const float* __restrict__ W,
                                               const float* __restrict__ b,
                                               const float* __restrict__ gam,
                                               const float* __restrict__ bet) {
    constexpr int KK = 32;            // k slab
    constexpr int CT = DO / 4;        // col threads (32 or 16)
    constexpr int RT = 256 / CT;      // row threads (8 or 16)
    constexpr int MT = RT * 8;        // nodes per block (64 or 128)
    constexpr int K4 = KK / 4;
    __shared__ __align__(16) float hs[KK][MT + 4];  // transposed h slab (row = 16B mult)
    __shared__ __align__(16) float ws[KK * DO];     // w slab

    int tid = threadIdx.x;
    int tx = tid % CT;
    int ty = tid / CT;
    int n0 = blockIdx.x * MT;

    unsigned long long acc2[8][2];
#pragma unroll
    for (int i = 0; i < 8; i++) {
        acc2[i][0] = 0ull;
        acc2[i][1] = 0ull;
    }

    for (int k0 = 0; k0 < DI; k0 += KK) {
        // stage h slab transposed: hs[k][n_local]
        for (int it = tid; it < MT * K4; it += 256) {
            int nl = it / K4;
            int k4 = it % K4;
            int n = n0 + nl;
            if (n >= NN) n = NN - 1;
            float4 v = __ldg((const float4*)&h[n * DI + k0 + 4 * k4]);
            hs[4 * k4 + 0][nl] = v.x;
            hs[4 * k4 + 1][nl] = v.y;
            hs[4 * k4 + 2][nl] = v.z;
            hs[4 * k4 + 3][nl] = v.w;
        }
        // stage w slab
        for (int it = tid; it < KK * DO / 4; it += 256)
            ((float4*)ws)[it] = __ldg(&((const float4*)(W + k0 * DO))[it]);
        __syncthreads();

#pragma unroll
        for (int k = 0; k < KK; k++) {
            ulonglong2 w2 = *(const ulonglong2*)&ws[k * DO + 4 * tx];  // {c0,c1},{c2,c3}
            float4 hA = *(const float4*)&hs[k][8 * ty];
            float4 hB = *(const float4*)&hs[k][8 * ty + 4];
            float hr[8] = {hA.x, hA.y, hA.z, hA.w, hB.x, hB.y, hB.z, hB.w};
#pragma unroll
            for (int i = 0; i < 8; i++) {
                unsigned long long hp = pack2(hr[i]);
                fma2(acc2[i][0], hp, w2.x);
                fma2(acc2[i][1], hp, w2.y);
            }
        }
        __syncthreads();
    }

    float4 bb = EPI ? __ldg((const float4*)&b[4 * tx]) : make_float4(0, 0, 0, 0);
    float4 gg = (EPI && BN) ? __ldg((const float4*)&gam[4 * tx]) : make_float4(0, 0, 0, 0);
    float4 be = (EPI && BN) ? __ldg((const float4*)&bet[4 * tx]) : make_float4(0, 0, 0, 0);
    float* dstp = EPI ? g_h : g_t;
#pragma unroll
    for (int i = 0; i < 8; i++) {
        int n = n0 + 8 * ty + i;
        if (n < NN) {
            float a0, a1, a2, a3;
            unpack2(acc2[i][0], a0, a1);
            unpack2(acc2[i][1], a2, a3);
            float4 o;
            if (EPI) {
                float di = g_dinv[n];
                o.x = di * gelu_bn(a0, bb.x, gg.x, be.x, BN);
                o.y = di * gelu_bn(a1, bb.y, gg.y, be.y, BN);
                o.z = di * gelu_bn(a2, bb.z, gg.z, be.z, BN);
                o.w = di * gelu_bn(a3, bb.w, gg.w, be.w, BN);
            } else {
                o = make_float4(a0, a1, a2, a3);
            }
            *(float4*)&dstp[n * DO + 4 * tx] = o;
        }
    }
}

// ---------------- pool encoding ---------------------------------------------
__device__ __forceinline__ unsigned fenc(float x) {
    unsigned u = __float_as_uint(x);
    return (u & 0x80000000u) ? ~u : (u | 0x80000000u);
}
__device__ __forceinline__ float fdec(unsigned u) {
    return (u & 0x80000000u) ? __uint_as_float(u & 0x7fffffffu) : __uint_as_float(~u);
}

// ---------------- L5: aggregate gemm output + bias + BN + GELU + pool -------
__global__ void __launch_bounds__(256) k_aggr_post(const float* __restrict__ b,
                                                   const float* __restrict__ gam,
                                                   const float* __restrict__ bet,
                                                   const int* __restrict__ batch) {
    int lane = threadIdx.x & 31;
    int warp = threadIdx.x >> 5;
    int n = blockIdx.x * 8 + warp;
    if (n >= NN) return;
    const float2* T = (const float2*)g_t;
    float2 a0 = T[n * 32 + lane];
    float2 a1 = make_float2(0.f, 0.f);
    int e = g_off[n];
    int r1 = e + g_degi[n];
    for (; e + 1 < r1; e += 2) {
        float2 v0 = __ldg(&T[g_csrc[e] * 32 + lane]);
        float2 v1 = __ldg(&T[g_csrc[e + 1] * 32 + lane]);
        a0.x += v0.x; a0.y += v0.y;
        a1.x += v1.x; a1.y += v1.y;
    }
    if (e < r1) {
        float2 v0 = __ldg(&T[g_csrc[e] * 32 + lane]);
        a0.x += v0.x; a0.y += v0.y;
    }
    float di = g_dinv[n];
    int gb = batch[n];
    float2 bb = __ldg(&((const float2*)b)[lane]);
    float2 gg = __ldg(&((const float2*)gam)[lane]);
    float2 be = __ldg(&((const float2*)bet)[lane]);
    float v0 = gelu_bn(di * (a0.x + a1.x), bb.x, gg.x, be.x, true);
    float v1 = gelu_bn(di * (a0.y + a1.y), bb.y, gg.y, be.y, true);
    atomicMax(&g_pool[gb * 64 + 2 * lane + 0], fenc(v0));
    atomicMax(&g_pool[gb * 64 + 2 * lane + 1], fenc(v1));
}

// ---------------- MLP head --------------------------------------------------
__global__ void __launch_bounds__(256) k_head(const float* __restrict__ lw1,
                                              const float* __restrict__ lb1,
                                              const float* __restrict__ lw2,
                                              const float* __restrict__ lb2,
                                              float* __restrict__ out) {
    int g = blockIdx.x * blockDim.x + threadIdx.x;
    if (g < GG) {
        float p[64];
#pragma unroll
        for (int d = 0; d < 64; d++) p[d] = fdec(g_pool[g * 64 + d]);
        float o0 = lb2[0];
        float o1 = lb2[1];
#pragma unroll
        for (int j = 0; j < 10; j++) {
            float hj = lb1[j];
#pragma unroll
            for (int d = 0; d < 64; d++) hj += p[d] * lw1[d * 10 + j];
            o0 += hj * lw2[j * 2 + 0];
            o1 += hj * lw2[j * 2 + 1];
        }
        out[g * 2 + 0] = o0;
        out[g * 2 + 1] = o1;
    }
}

extern "C" void kernel_launch(void* const* d_in, const int* in_sizes, int n_in,
                              void* d_out, int out_size) {
    const float* x = (const float*)d_in[0];
    const int* ei = (const int*)d_in[1];
    const int* src = ei;        // ei[0]
    const int* dst = ei + EE;   // ei[1]
    const int* batch = (const int*)d_in[2];
    const float* W1 = (const float*)d_in[3];
    const float* b1 = (const float*)d_in[4];
    const float* W2 = (const float*)d_in[5];
    const float* b2 = (const float*)d_in[6];
    const float* W3 = (const float*)d_in[7];
    const float* b3 = (const float*)d_in[8];
    const float* W4 = (const float*)d_in[9];
    const float* b4 = (const float*)d_in[10];
    const float* W5 = (const float*)d_in[11];
    const float* b5 = (const float*)d_in[12];
    const float* g1 = (const float*)d_in[13];
    const float* be1 = (const float*)d_in[14];
    const float* g2 = (const float*)d_in[15];
    const float* be2 = (const float*)d_in[16];
    const float* g3 = (const float*)d_in[17];
    const float* be3 = (const float*)d_in[18];
    const float* lw1 = (const float*)d_in[19];
    const float* lb1 = (const float*)d_in[20];
    const float* lw2 = (const float*)d_in[21];
    const float* lb2 = (const float*)d_in[22];
    float* out = (float*)d_out;

    float* aptr = nullptr;
    float* hptr = nullptr;
    cudaGetSymbolAddress((void**)&aptr, g_a);
    cudaGetSymbolAddress((void**)&hptr, g_h);

    // CSR build
    k_zero<<<(NN + 255) / 256, 256>>>();
    k_deg<<<(EE + 255) / 256, 256>>>(dst);
    k_prep<<<(NN + 255) / 256, 256>>>(x);
    k_fill<<<(EE + 255) / 256, 256>>>(src, dst);

    // L1: aggregate (DI=2) then tiny GEMM 2->64 + BN + GELU + dinv
    k_aggr_pre2<<<(NN + 255) / 256, 256>>>();
    k_l1<<<(NN + 7) / 8, 256>>>(W1, b1, g1, be1);
    // L2: aggregate(64) then GEMM 64->64 + GELU + dinv  (MT=128)
    k_aggr64<<<(NN + 7) / 8, 256>>>(hptr, aptr);
    k_gemmT<64, 64, true, false><<<(NN + 127) / 128, 256>>>(aptr, W2, b2, nullptr, nullptr);
    // L3: aggregate(64) then GEMM 64->128 + BN + GELU + dinv  (MT=64)
    k_aggr64<<<(NN + 7) / 8, 256>>>(hptr, aptr);
    k_gemmT<64, 128, true, true><<<(NN + 63) / 64, 256>>>(aptr, W3, b3, g2, be2);
    // L4: aggregate(128) then GEMM 128->128 + GELU + dinv  (MT=64)
    k_aggr128<<<(NN + 7) / 8, 256>>>();
    k_gemmT<128, 128, true, false><<<(NN + 63) / 64, 256>>>(aptr, W4, b4, nullptr, nullptr);
    // L5: GEMM 128->64 (plain, MT=128) then aggregate(64)+bias+BN+GELU+pool
    k_gemmT<128, 64, false, false><<<(NN + 127) / 128, 256>>>(hptr, W5, nullptr, nullptr, nullptr);
    k_aggr_post<<<(NN + 7) / 8, 256>>>(b5, g3, be3, batch);

    k_head<<<2, 256>>>(lw1, lb1, lw2, lb2, out);
}

// round 11
// speedup vs baseline: 5.7325x; 1.0438x over previous
#include <cuda_runtime.h>
#include <cuda_fp16.h>
#include <math.h>

#define NN 100000
#define EE 1600000
#define GG 512

// ---------------- scratch (device globals; no allocation allowed) ----------
__device__ float g_h[NN * 128];              // fp32 activations (L1-in 2wide, L4 out)
__device__ float g_a[NN * 128];              // aggregated (pre-GEMM) features, fp32
__device__ __align__(16) unsigned g_hh[NN * 64];  // half2-packed activations for gathers
__device__ float g_dinv[NN];
__device__ int   g_degi[NN];
__device__ int   g_off[NN];
__device__ int   g_cursor[NN];
__device__ int   g_csrc[EE];
__device__ int   g_ctr;
__device__ unsigned g_pool[GG * 64];

// ---------------- packed f32x2 helpers (Blackwell FFMA2) --------------------
__device__ __forceinline__ unsigned long long pack2(float v) {
    unsigned long long r;
    asm("mov.b64 %0, {%1, %1};" : "=l"(r) : "f"(v));
    return r;
}
__device__ __forceinline__ void unpack2(unsigned long long v, float& lo, float& hi) {
    asm("mov.b64 {%0, %1}, %2;" : "=f"(lo), "=f"(hi) : "l"(v));
}
__device__ __forceinline__ void fma2(unsigned long long& d, unsigned long long a,
                                     unsigned long long b) {
    asm("fma.rn.f32x2 %0, %1, %2, %0;" : "+l"(d) : "l"(a), "l"(b));
}
__device__ __forceinline__ float2 h2f(unsigned v) {
    return __half22float2(*(__half2*)&v);
}
__device__ __forceinline__ unsigned f2h(float a, float b) {
    __half2 p = __floats2half2_rn(a, b);
    return *(unsigned*)&p;
}

// ---------------- CSR build --------------------------------------------------
__global__ void __launch_bounds__(256) k_zero() {
    int i = blockIdx.x * blockDim.x + threadIdx.x;
    if (i < NN) g_degi[i] = 0;
    if (i < GG * 64) g_pool[i] = 0u;
    if (i == 0) g_ctr = 0;
}
__global__ void __launch_bounds__(256) k_deg(const int* __restrict__ dst) {
    int e = blockIdx.x * blockDim.x + threadIdx.x;
    if (e < EE) atomicAdd(&g_degi[dst[e]], 1);
}
__global__ void __launch_bounds__(256) k_prep(const float* __restrict__ x) {
    int i = blockIdx.x * 256 + threadIdx.x;
    int lane = threadIdx.x & 31;
    int w = threadIdx.x >> 5;
    int v = (i < NN) ? g_degi[i] : 0;
    if (i < NN) {
        float di = rsqrtf((float)v + 1.0f);  // +1 self loop
        g_dinv[i] = di;
        g_h[i * 2 + 0] = di * x[i * 2 + 0];
        g_h[i * 2 + 1] = di * x[i * 2 + 1];
    }
    int xs = v;
#pragma unroll
    for (int o = 1; o < 32; o <<= 1) {
        int y = __shfl_up_sync(0xffffffffu, xs, o);
        if (lane >= o) xs += y;
    }
    __shared__ int ws[8];
    __shared__ int base;
    if (lane == 31) ws[w] = xs;
    __syncthreads();
    if (w == 0) {
        int s = (lane < 8) ? ws[lane] : 0;
#pragma unroll
        for (int o = 1; o < 8; o <<= 1) {
            int y = __shfl_up_sync(0xffffffffu, s, o);
            if (lane >= o) s += y;
        }
        if (lane < 8) ws[lane] = s;
    }
    __syncthreads();
    if (threadIdx.x == 0) base = atomicAdd(&g_ctr, ws[7]);
    int excl = xs - v + ((w > 0) ? ws[w - 1] : 0);
    __syncthreads();
    if (i < NN) {
        int off = base + excl;
        g_off[i] = off;
        g_cursor[i] = off;
    }
}
__global__ void __launch_bounds__(256) k_fill(const int* __restrict__ src,
                                              const int* __restrict__ dst) {
    int e = blockIdx.x * blockDim.x + threadIdx.x;
    if (e < EE) {
        int pos = atomicAdd(&g_cursor[dst[e]], 1);
        g_csrc[pos] = src[e];
    }
}

// ---------------- aggregation (fp16 gathers, fp32 accumulate) ---------------
// DI=2: thread per node (fp32 — trivial traffic)
__global__ void __launch_bounds__(256) k_aggr_pre2() {
    int n = blockIdx.x * blockDim.x + threadIdx.x;
    if (n >= NN) return;
    const float2* hh = (const float2*)g_h;
    float2 acc = hh[n];
    int e = g_off[n];
    int r1 = e + g_degi[n];
    for (; e < r1; e++) {
        float2 v = __ldg(&hh[g_csrc[e]]);
        acc.x += v.x;
        acc.y += v.y;
    }
    float di = g_dinv[n];
    g_a[n * 2 + 0] = di * acc.x;
    g_a[n * 2 + 1] = di * acc.y;
}

// D=64 half rows (stride 32 half2): warp per node, lane owns half2 {2l,2l+1}
__global__ void __launch_bounds__(256) k_aggr64h(float* __restrict__ outp) {
    int lane = threadIdx.x & 31;
    int warp = threadIdx.x >> 5;
    int n = blockIdx.x * 8 + warp;
    if (n >= NN) return;
    float2 f = h2f(g_hh[n * 32 + lane]);   // self term
    float ax = f.x, ay = f.y, bx = 0.f, by = 0.f;
    int e = g_off[n];
    int r1 = e + g_degi[n];
    for (; e + 3 < r1; e += 4) {
        unsigned v0 = __ldg(&g_hh[g_csrc[e] * 32 + lane]);
        unsigned v1 = __ldg(&g_hh[g_csrc[e + 1] * 32 + lane]);
        unsigned v2 = __ldg(&g_hh[g_csrc[e + 2] * 32 + lane]);
        unsigned v3 = __ldg(&g_hh[g_csrc[e + 3] * 32 + lane]);
        float2 f0 = h2f(v0), f1 = h2f(v1), f2 = h2f(v2), f3 = h2f(v3);
        ax += f0.x + f2.x; ay += f0.y + f2.y;
        bx += f1.x + f3.x; by += f1.y + f3.y;
    }
    for (; e < r1; e++) {
        float2 f0 = h2f(__ldg(&g_hh[g_csrc[e] * 32 + lane]));
        ax += f0.x; ay += f0.y;
    }
    float di = g_dinv[n];
    ((float2*)outp)[n * 32 + lane] = make_float2(di * (ax + bx), di * (ay + by));
}

// D=128 half rows (stride 32 uint2): lane owns cols {4l..4l+3}
__global__ void __launch_bounds__(256) k_aggr128h() {
    int lane = threadIdx.x & 31;
    int warp = threadIdx.x >> 5;
    int n = blockIdx.x * 8 + warp;
    if (n >= NN) return;
    const uint2* H = (const uint2*)g_hh;
    uint2 sv = H[n * 32 + lane];
    float2 fa = h2f(sv.x), fb = h2f(sv.y);
    float a0 = fa.x, a1 = fa.y, a2 = fb.x, a3 = fb.y;
    float b0 = 0.f, b1 = 0.f, b2 = 0.f, b3 = 0.f;
    int e = g_off[n];
    int r1 = e + g_degi[n];
    for (; e + 3 < r1; e += 4) {
        uint2 v0 = __ldg(&H[g_csrc[e] * 32 + lane]);
        uint2 v1 = __ldg(&H[g_csrc[e + 1] * 32 + lane]);
        uint2 v2 = __ldg(&H[g_csrc[e + 2] * 32 + lane]);
        uint2 v3 = __ldg(&H[g_csrc[e + 3] * 32 + lane]);
        float2 p;
        p = h2f(v0.x); a0 += p.x; a1 += p.y;
        p = h2f(v0.y); a2 += p.x; a3 += p.y;
        p = h2f(v1.x); b0 += p.x; b1 += p.y;
        p = h2f(v1.y); b2 += p.x; b3 += p.y;
        p = h2f(v2.x); a0 += p.x; a1 += p.y;
        p = h2f(v2.y); a2 += p.x; a3 += p.y;
        p = h2f(v3.x); b0 += p.x; b1 += p.y;
        p = h2f(v3.y); b2 += p.x; b3 += p.y;
    }
    for (; e < r1; e++) {
        uint2 v0 = __ldg(&H[g_csrc[e] * 32 + lane]);
        float2 p;
        p = h2f(v0.x); a0 += p.x; a1 += p.y;
        p = h2f(v0.y); a2 += p.x; a3 += p.y;
    }
    float di = g_dinv[n];
    ((float4*)g_a)[n * 32 + lane] = make_float4(di * (a0 + b0), di * (a1 + b1),
                                                di * (a2 + b2), di * (a3 + b3));
}

// ---------------- epilogue helper -------------------------------------------
__device__ __forceinline__ float gelu_bn(float x, float bb, float gg, float be, bool bn) {
    x = x + bb;
    if (bn) x = x * (gg * 0.99999500003749973f) + be;
    return 0.5f * x * (1.0f + erff(x * 0.70710678118654752f));
}

// ---------------- L1: out = epi(a @ W1), half output ------------------------
__global__ void __launch_bounds__(256) k_l1(const float* __restrict__ W,
                                            const float* __restrict__ b,
                                            const float* __restrict__ gam,
                                            const float* __restrict__ bet) {
    int lane = threadIdx.x & 31;
    int warp = threadIdx.x >> 5;
    int n = blockIdx.x * 8 + warp;
    if (n >= NN) return;
    float2 a = ((const float2*)g_a)[n];
    float2 w0 = __ldg(&((const float2*)W)[lane]);
    float2 w1 = __ldg(&((const float2*)(W + 64))[lane]);
    float2 bb = __ldg(&((const float2*)b)[lane]);
    float2 gg = __ldg(&((const float2*)gam)[lane]);
    float2 be = __ldg(&((const float2*)bet)[lane]);
    float di = g_dinv[n];
    float x0 = a.x * w0.x + a.y * w1.x;
    float x1 = a.x * w0.y + a.y * w1.y;
    x0 = di * gelu_bn(x0, bb.x, gg.x, be.x, true);
    x1 = di * gelu_bn(x1, bb.y, gg.y, be.y, true);
    g_hh[n * 32 + lane] = f2h(x0, x1);
}

// ---------------- register-tiled outer-product GEMM (FFMA2) -----------------
// OUTH=true -> half2 output to g_hh ; OUTH=false -> fp32 to g_h
template <int DI, int DO, bool EPI, bool BN, bool OUTH>
__global__ void __launch_bounds__(256) k_gemmT(const float* __restrict__ h,
                                               const float* __restrict__ W,
                                               const float* __restrict__ b,
                                               const float* __restrict__ gam,
                                               const float* __restrict__ bet) {
    constexpr int KK = 32;
    constexpr int CT = DO / 4;
    constexpr int RT = 256 / CT;
    constexpr int MT = RT * 8;
    constexpr int K4 = KK / 4;
    __shared__ __align__(16) float hs[KK][MT + 4];
    __shared__ __align__(16) float ws[KK * DO];

    int tid = threadIdx.x;
    int tx = tid % CT;
    int ty = tid / CT;
    int n0 = blockIdx.x * MT;

    unsigned long long acc2[8][2];
#pragma unroll
    for (int i = 0; i < 8; i++) {
        acc2[i][0] = 0ull;
        acc2[i][1] = 0ull;
    }

    for (int k0 = 0; k0 < DI; k0 += KK) {
        for (int it = tid; it < MT * K4; it += 256) {
            int nl = it / K4;
            int k4 = it % K4;
            int n = n0 + nl;
            if (n >= NN) n = NN - 1;
            float4 v = __ldg((const float4*)&h[n * DI + k0 + 4 * k4]);
            hs[4 * k4 + 0][nl] = v.x;
            hs[4 * k4 + 1][nl] = v.y;
            hs[4 * k4 + 2][nl] = v.z;
            hs[4 * k4 + 3][nl] = v.w;
        }
        for (int it = tid; it < KK * DO / 4; it += 256)
            ((float4*)ws)[it] = __ldg(&((const float4*)(W + k0 * DO))[it]);
        __syncthreads();

#pragma unroll
        for (int k = 0; k < KK; k++) {
            ulonglong2 w2 = *(const ulonglong2*)&ws[k * DO + 4 * tx];
            float4 hA = *(const float4*)&hs[k][8 * ty];
            float4 hB = *(const float4*)&hs[k][8 * ty + 4];
            float hr[8] = {hA.x, hA.y, hA.z, hA.w, hB.x, hB.y, hB.z, hB.w};
#pragma unroll
            for (int i = 0; i < 8; i++) {
                unsigned long long hp = pack2(hr[i]);
                fma2(acc2[i][0], hp, w2.x);
                fma2(acc2[i][1], hp, w2.y);
            }
        }
        __syncthreads();
    }

    float4 bb = EPI ? __ldg((const float4*)&b[4 * tx]) : make_float4(0, 0, 0, 0);
    float4 gg = (EPI && BN) ? __ldg((const float4*)&gam[4 * tx]) : make_float4(0, 0, 0, 0);
    float4 be = (EPI && BN) ? __ldg((const float4*)&bet[4 * tx]) : make_float4(0, 0, 0, 0);
#pragma unroll
    for (int i = 0; i < 8; i++) {
        int n = n0 + 8 * ty + i;
        if (n < NN) {
            float a0, a1, a2, a3;
            unpack2(acc2[i][0], a0, a1);
            unpack2(acc2[i][1], a2, a3);
            float4 o;
            if (EPI) {
                float di = g_dinv[n];
                o.x = di * gelu_bn(a0, bb.x, gg.x, be.x, BN);
                o.y = di * gelu_bn(a1, bb.y, gg.y, be.y, BN);
                o.z = di * gelu_bn(a2, bb.z, gg.z, be.z, BN);
                o.w = di * gelu_bn(a3, bb.w, gg.w, be.w, BN);
            } else {
                o = make_float4(a0, a1, a2, a3);
            }
            if (OUTH) {
                uint2 u = make_uint2(f2h(o.x, o.y), f2h(o.z, o.w));
                ((uint2*)g_hh)[n * (DO / 4) + tx] = u;
            } else {
                *(float4*)&g_h[n * DO + 4 * tx] = o;
            }
        }
    }
}

// ---------------- pool encoding ---------------------------------------------
__device__ __forceinline__ unsigned fenc(float x) {
    unsigned u = __float_as_uint(x);
    return (u & 0x80000000u) ? ~u : (u | 0x80000000u);
}
__device__ __forceinline__ float fdec(unsigned u) {
    return (u & 0x80000000u) ? __uint_as_float(u & 0x7fffffffu) : __uint_as_float(~u);
}

// ---------------- L5: aggregate (half) + bias + BN + GELU + pool ------------
__global__ void __launch_bounds__(256) k_aggr_post(const float* __restrict__ b,
                                                   const float* __restrict__ gam,
                                                   const float* __restrict__ bet,
                                                   const int* __restrict__ batch) {
    int lane = threadIdx.x & 31;
    int warp = threadIdx.x >> 5;
    int n = blockIdx.x * 8 + warp;
    if (n >= NN) return;
    float2 f = h2f(g_hh[n * 32 + lane]);
    float ax = f.x, ay = f.y, bx = 0.f, by = 0.f;
    int e = g_off[n];
    int r1 = e + g_degi[n];
    for (; e + 3 < r1; e += 4) {
        unsigned v0 = __ldg(&g_hh[g_csrc[e] * 32 + lane]);
        unsigned v1 = __ldg(&g_hh[g_csrc[e + 1] * 32 + lane]);
        unsigned v2 = __ldg(&g_hh[g_csrc[e + 2] * 32 + lane]);
        unsigned v3 = __ldg(&g_hh[g_csrc[e + 3] * 32 + lane]);
        float2 f0 = h2f(v0), f1 = h2f(v1), f2 = h2f(v2), f3 = h2f(v3);
        ax += f0.x + f2.x; ay += f0.y + f2.y;
        bx += f1.x + f3.x; by += f1.y + f3.y;
    }
    for (; e < r1; e++) {
        float2 f0 = h2f(__ldg(&g_hh[g_csrc[e] * 32 + lane]));
        ax += f0.x; ay += f0.y;
    }
    float di = g_dinv[n];
    int gb = batch[n];
    float2 bb = __ldg(&((const float2*)b)[lane]);
    float2 gg = __ldg(&((const float2*)gam)[lane]);
    float2 be = __ldg(&((const float2*)bet)[lane]);
    float v0 = gelu_bn(di * (ax + bx), bb.x, gg.x, be.x, true);
    float v1 = gelu_bn(di * (ay + by), bb.y, gg.y, be.y, true);
    atomicMax(&g_pool[gb * 64 + 2 * lane + 0], fenc(v0));
    atomicMax(&g_pool[gb * 64 + 2 * lane + 1], fenc(v1));
}

// ---------------- MLP head --------------------------------------------------
__global__ void __launch_bounds__(256) k_head(const float* __restrict__ lw1,
                                              const float* __restrict__ lb1,
                                              const float* __restrict__ lw2,
                                              const float* __restrict__ lb2,
                                              float* __restrict__ out) {
    int g = blockIdx.x * blockDim.x + threadIdx.x;
    if (g < GG) {
        float p[64];
#pragma unroll
        for (int d = 0; d < 64; d++) p[d] = fdec(g_pool[g * 64 + d]);
        float o0 = lb2[0];
        float o1 = lb2[1];
#pragma unroll
        for (int j = 0; j < 10; j++) {
            float hj = lb1[j];
#pragma unroll
            for (int d = 0; d < 64; d++) hj += p[d] * lw1[d * 10 + j];
            o0 += hj * lw2[j * 2 + 0];
            o1 += hj * lw2[j * 2 + 1];
        }
        out[g * 2 + 0] = o0;
        out[g * 2 + 1] = o1;
    }
}

extern "C" void kernel_launch(void* const* d_in, const int* in_sizes, int n_in,
                              void* d_out, int out_size) {
    const float* x = (const float*)d_in[0];
    const int* ei = (const int*)d_in[1];
    const int* src = ei;
    const int* dst = ei + EE;
    const int* batch = (const int*)d_in[2];
    const float* W1 = (const float*)d_in[3];
    const float* b1 = (const float*)d_in[4];
    const float* W2 = (const float*)d_in[5];
    const float* b2 = (const float*)d_in[6];
    const float* W3 = (const float*)d_in[7];
    const float* b3 = (const float*)d_in[8];
    const float* W4 = (const float*)d_in[9];
    const float* b4 = (const float*)d_in[10];
    const float* W5 = (const float*)d_in[11];
    const float* b5 = (const float*)d_in[12];
    const float* g1 = (const float*)d_in[13];
    const float* be1 = (const float*)d_in[14];
    const float* g2 = (const float*)d_in[15];
    const float* be2 = (const float*)d_in[16];
    const float* g3 = (const float*)d_in[17];
    const float* be3 = (const float*)d_in[18];
    const float* lw1 = (const float*)d_in[19];
    const float* lb1 = (const float*)d_in[20];
    const float* lw2 = (const float*)d_in[21];
    const float* lb2 = (const float*)d_in[22];
    float* out = (float*)d_out;

    float* aptr = nullptr;
    float* hptr = nullptr;
    cudaGetSymbolAddress((void**)&aptr, g_a);
    cudaGetSymbolAddress((void**)&hptr, g_h);

    // CSR build
    k_zero<<<(NN + 255) / 256, 256>>>();
    k_deg<<<(EE + 255) / 256, 256>>>(dst);
    k_prep<<<(NN + 255) / 256, 256>>>(x);
    k_fill<<<(EE + 255) / 256, 256>>>(src, dst);

    // L1: aggregate (DI=2, fp32) then tiny GEMM 2->64 + BN + GELU + dinv -> half
    k_aggr_pre2<<<(NN + 255) / 256, 256>>>();
    k_l1<<<(NN + 7) / 8, 256>>>(W1, b1, g1, be1);
    // L2: aggregate(64, half) then GEMM 64->64 + GELU + dinv -> half
    k_aggr64h<<<(NN + 7) / 8, 256>>>(aptr);
    k_gemmT<64, 64, true, false, true><<<(NN + 127) / 128, 256>>>(aptr, W2, b2, nullptr, nullptr);
    // L3: aggregate(64, half) then GEMM 64->128 + BN + GELU + dinv -> half
    k_aggr64h<<<(NN + 7) / 8, 256>>>(aptr);
    k_gemmT<64, 128, true, true, true><<<(NN + 63) / 64, 256>>>(aptr, W3, b3, g2, be2);
    // L4: aggregate(128, half) then GEMM 128->128 + GELU + dinv -> fp32 (dense reuse)
    k_aggr128h<<<(NN + 7) / 8, 256>>>();
    k_gemmT<128, 128, true, false, false><<<(NN + 63) / 64, 256>>>(aptr, W4, b4, nullptr, nullptr);
    // L5: GEMM 128->64 (raw acc -> half) then aggregate+bias+BN+GELU+pool
    k_gemmT<128, 64, false, false, true><<<(NN + 127) / 128, 256>>>(hptr, W5, nullptr, nullptr, nullptr);
    k_aggr_post<<<(NN + 7) / 8, 256>>>(b5, g3, be3, batch);

    k_head<<<2, 256>>>(lw1, lb1, lw2, lb2, out);
}